// round 8
// baseline (speedup 1.0000x reference)
#include <cuda_runtime.h>
#include <cuda_bf16.h>
#include <math.h>
#include <stdint.h>

#define L_TOK 3840
#define DIM   1536
#define NH    12
#define HD    128
#define FRAME 480
#define NPAIR 64

// ---------------- device scratch (no allocs allowed) ----------------
__device__ float g_q[L_TOK * DIM];
__device__ float g_k[L_TOK * DIM];
__device__ float g_cos[L_TOK * NPAIR];
__device__ float g_sin[L_TOK * NPAIR];
__device__ __nv_bfloat16 g_ah[L_TOK * DIM];      // GEMM A hi (x, later attn out)
__device__ __nv_bfloat16 g_al[L_TOK * DIM];      // GEMM A lo
__device__ __nv_bfloat16 g_wh[4][DIM * DIM];     // W^T hi  [N][K] for q,k,v,o
__device__ __nv_bfloat16 g_wl[4][DIM * DIM];     // W^T lo
__device__ __nv_bfloat16 g_qh[L_TOK * DIM];
__device__ __nv_bfloat16 g_ql[L_TOK * DIM];
__device__ __nv_bfloat16 g_kh[L_TOK * DIM];
__device__ __nv_bfloat16 g_kl[L_TOK * DIM];
__device__ __nv_bfloat16 g_vh[L_TOK * DIM];
__device__ __nv_bfloat16 g_vl[L_TOK * DIM];

// =================== sm_80-era PTX helpers (valid on plain sm_103) ==========
__device__ __forceinline__ uint32_t smem_u32(const void* p) {
    uint32_t a;
    asm("{ .reg .u64 t; cvta.to.shared.u64 t, %1; cvt.u32.u64 %0, t; }" : "=r"(a) : "l"(p));
    return a;
}
#define CP_ASYNC16(dst, src) \
    asm volatile("cp.async.cg.shared.global [%0], [%1], 16;" :: "r"(dst), "l"(src))
#define CP_COMMIT() asm volatile("cp.async.commit_group;" ::: "memory")
#define CP_WAIT2()  asm volatile("cp.async.wait_group 2;" ::: "memory")
#define CP_WAIT1()  asm volatile("cp.async.wait_group 1;" ::: "memory")
#define CP_WAIT0()  asm volatile("cp.async.wait_group 0;" ::: "memory")

__device__ __forceinline__ void ldsm4(uint32_t* r, uint32_t addr) {
    asm volatile("ldmatrix.sync.aligned.m8n8.x4.shared.b16 {%0,%1,%2,%3}, [%4];"
                 : "=r"(r[0]), "=r"(r[1]), "=r"(r[2]), "=r"(r[3]) : "r"(addr));
}
__device__ __forceinline__ void ldsm4t(uint32_t* r, uint32_t addr) {
    asm volatile("ldmatrix.sync.aligned.m8n8.x4.trans.shared.b16 {%0,%1,%2,%3}, [%4];"
                 : "=r"(r[0]), "=r"(r[1]), "=r"(r[2]), "=r"(r[3]) : "r"(addr));
}
__device__ __forceinline__ void mma16816(float* c, const uint32_t* a, const uint32_t* b) {
    asm volatile("mma.sync.aligned.m16n8k16.row.col.f32.bf16.bf16.f32 "
                 "{%0,%1,%2,%3}, {%4,%5,%6,%7}, {%8,%9}, {%0,%1,%2,%3};"
                 : "+f"(c[0]), "+f"(c[1]), "+f"(c[2]), "+f"(c[3])
                 : "r"(a[0]), "r"(a[1]), "r"(a[2]), "r"(a[3]), "r"(b[0]), "r"(b[1]));
}
#define SWZ128(off) ((off) ^ (((off) >> 3) & 0x70))

__device__ __forceinline__ uint32_t pack_bf16(float lo, float hi) {
    uint32_t r;
    asm("cvt.rn.bf16x2.f32 %0, %1, %2;" : "=r"(r) : "f"(hi), "f"(lo));
    return r;
}

// ---------------- angle table ----------------
__global__ void angles_kernel(const float* __restrict__ ff,
                              const float* __restrict__ fh,
                              const float* __restrict__ fw) {
    int idx = blockIdx.x * blockDim.x + threadIdx.x;
    if (idx >= L_TOK * NPAIR) return;
    int l = idx / NPAIR, j = idx % NPAIR;
    int f = l / FRAME, r = l % FRAME;
    int h = r / 30, w = r % 30;
    float a;
    if (j < 22)      a = ff[f * 22 + j];
    else if (j < 43) a = fh[h * 21 + (j - 22)];
    else             a = fw[w * 21 + (j - 43)];
    g_cos[idx] = cosf(a);
    g_sin[idx] = sinf(a);
}

// ---------------- split fp32 -> bf16 hi/lo ----------------
__global__ __launch_bounds__(256) void split_kernel(const float* __restrict__ x,
                                                    __nv_bfloat16* __restrict__ hi,
                                                    __nv_bfloat16* __restrict__ lo, int n) {
    int i = blockIdx.x * blockDim.x + threadIdx.x;
    if (i * 4 >= n) return;
    float4 v = *(const float4*)&x[i * 4];
    __nv_bfloat16 h0 = __float2bfloat16(v.x), h1 = __float2bfloat16(v.y);
    __nv_bfloat16 h2 = __float2bfloat16(v.z), h3 = __float2bfloat16(v.w);
    __nv_bfloat16 l0 = __float2bfloat16(v.x - __bfloat162float(h0));
    __nv_bfloat16 l1 = __float2bfloat16(v.y - __bfloat162float(h1));
    __nv_bfloat16 l2 = __float2bfloat16(v.z - __bfloat162float(h2));
    __nv_bfloat16 l3 = __float2bfloat16(v.w - __bfloat162float(h3));
    __nv_bfloat162* ph = (__nv_bfloat162*)&hi[i * 4];
    __nv_bfloat162* pl = (__nv_bfloat162*)&lo[i * 4];
    ph[0] = {h0, h1}; ph[1] = {h2, h3};
    pl[0] = {l0, l1}; pl[1] = {l2, l3};
}

// ------- fused transpose of 4 weights [K,N] -> [N,K] with hi/lo split -------
__global__ __launch_bounds__(256) void transpose_split4_kernel(
    const float* __restrict__ W0, const float* __restrict__ W1,
    const float* __restrict__ W2, const float* __restrict__ W3,
    __nv_bfloat16* __restrict__ ThBase, __nv_bfloat16* __restrict__ TlBase) {
    __shared__ float t[32][33];
    int z = blockIdx.z;
    const float* W = (z == 0) ? W0 : (z == 1) ? W1 : (z == 2) ? W2 : W3;
    __nv_bfloat16* Th = ThBase + (size_t)z * DIM * DIM;
    __nv_bfloat16* Tl = TlBase + (size_t)z * DIM * DIM;
    int tx = threadIdx.x, ty = threadIdx.y;  // 32 x 8
    int x0 = blockIdx.x * 32, y0 = blockIdx.y * 32;
#pragma unroll
    for (int i = 0; i < 32; i += 8)
        t[ty + i][tx] = W[(size_t)(y0 + ty + i) * DIM + x0 + tx];
    __syncthreads();
#pragma unroll
    for (int i = 0; i < 32; i += 8) {
        float v = t[tx][ty + i];
        __nv_bfloat16 h = __float2bfloat16(v);
        __nv_bfloat16 l = __float2bfloat16(v - __bfloat162float(h));
        size_t o = (size_t)(x0 + ty + i) * DIM + y0 + tx;
        Th[o] = h;
        Tl[o] = l;
    }
}

// ---------------- HMMA split-bf16 GEMM: 256 threads, 3-stage pipeline -------
// CTA tile 128x128, BK=64. 8 warps as 4m x 2n; warp tile 32x64 (R6 layout).
#define GK       64
#define TILE_B   16384
#define BUF_B    (4 * TILE_B)
#define NSTAGE   3
#define GSMEM    (1024 + NSTAGE * BUF_B)

struct GemmArgs {
    const __nv_bfloat16 *wh0, *wl0, *wh1, *wl1, *wh2, *wl2;
    const float *b0, *b1, *b2;
    float *o0, *o1;
    __nv_bfloat16 *ovh, *ovl;
};

__global__ __launch_bounds__(256, 1) void gemm_hmma(const __nv_bfloat16* __restrict__ Ah,
                                                    const __nv_bfloat16* __restrict__ Al,
                                                    GemmArgs ga) {
    extern __shared__ char dsm[];
    uint32_t raw = smem_u32(dsm);
    uint32_t sbase = (raw + 1023u) & ~1023u;

    int tid = threadIdx.x;
    int wid = tid >> 5, lane = tid & 31;
    int m0 = blockIdx.y * 128;
    int n0 = blockIdx.x * 128;

    const __nv_bfloat16 *Bh, *Bl;
    const float* bias;
    float* Cf;
    if (blockIdx.z == 0)      { Bh = ga.wh0; Bl = ga.wl0; bias = ga.b0; Cf = ga.o0; }
    else if (blockIdx.z == 1) { Bh = ga.wh1; Bl = ga.wl1; bias = ga.b1; Cf = ga.o1; }
    else                      { Bh = ga.wh2; Bl = ga.wl2; bias = ga.b2; Cf = nullptr; }

    const __nv_bfloat16* srcs[4] = {Ah, Al, Bh, Bl};
    const int rbase[4] = {m0, m0, n0, n0};

    auto load_chunk = [&](int c, int buf) {
        uint32_t dst0 = sbase + (uint32_t)buf * BUF_B;
#pragma unroll
        for (int it = 0; it < 16; it++) {
            int idx = it * 256 + tid;
            int tile = idx >> 10;
            int rem = idx & 1023;
            int r = rem >> 3, g = rem & 7;
            const __nv_bfloat16* src = srcs[tile] + (size_t)(rbase[tile] + r) * DIM + c * GK + g * 8;
            uint32_t off = (uint32_t)(r * 128 + g * 16);
            CP_ASYNC16(dst0 + (uint32_t)tile * TILE_B + SWZ128(off), src);
        }
    };

    float Creg[2][8][4];
#pragma unroll
    for (int mt = 0; mt < 2; mt++)
#pragma unroll
        for (int nf = 0; nf < 8; nf++)
#pragma unroll
            for (int j = 0; j < 4; j++) Creg[mt][nf][j] = 0.f;

    int m_base = (wid & 3) * 32;
    int n_base = (wid >> 2) * 64;
    int a_r = m_base + (lane & 7) + ((lane >> 3) & 1) * 8;
    int a_g = (lane >> 4);
    int b_r = n_base + ((lane >> 4) & 1) * 8 + (lane & 7);
    int b_g = (lane >> 3) & 1;

    const int NCH = DIM / GK;  // 24
    load_chunk(0, 0); CP_COMMIT();
    load_chunk(1, 1); CP_COMMIT();
    load_chunk(2, 2); CP_COMMIT();

    int buf = 0;
    for (int c = 0; c < NCH; c++) {
        if (c + 2 < NCH) CP_WAIT2();
        else if (c + 1 < NCH) CP_WAIT1();
        else CP_WAIT0();
        __syncthreads();

        uint32_t sb = sbase + (uint32_t)buf * BUF_B;
        uint32_t sAh = sb, sAl = sb + TILE_B, sBh = sb + 2 * TILE_B, sBl = sb + 3 * TILE_B;

#pragma unroll
        for (int ks = 0; ks < 4; ks++) {
            uint32_t ah[2][4], al[2][4], bh[16], bl[16];
#pragma unroll
            for (int mt = 0; mt < 2; mt++) {
                uint32_t off = SWZ128((uint32_t)((a_r + mt * 16) * 128 + (a_g + 2 * ks) * 16));
                ldsm4(ah[mt], sAh + off);
                ldsm4(al[mt], sAl + off);
            }
#pragma unroll
            for (int nf2 = 0; nf2 < 4; nf2++) {
                uint32_t off = SWZ128((uint32_t)((b_r + nf2 * 16) * 128 + (b_g + 2 * ks) * 16));
                ldsm4(&bh[nf2 * 4], sBh + off);
                ldsm4(&bl[nf2 * 4], sBl + off);
            }
#pragma unroll
            for (int nf = 0; nf < 8; nf++)
#pragma unroll
                for (int mt = 0; mt < 2; mt++)
                    mma16816(Creg[mt][nf], ah[mt], &bh[nf * 2]);
#pragma unroll
            for (int nf = 0; nf < 8; nf++)
#pragma unroll
                for (int mt = 0; mt < 2; mt++)
                    mma16816(Creg[mt][nf], ah[mt], &bl[nf * 2]);
#pragma unroll
            for (int nf = 0; nf < 8; nf++)
#pragma unroll
                for (int mt = 0; mt < 2; mt++)
                    mma16816(Creg[mt][nf], al[mt], &bh[nf * 2]);
        }
        __syncthreads();
        if (c + 3 < NCH) { load_chunk(c + 3, buf); CP_COMMIT(); }
        buf = (buf == 2) ? 0 : buf + 1;
    }

#pragma unroll
    for (int mt = 0; mt < 2; mt++) {
#pragma unroll
        for (int nf = 0; nf < 8; nf++) {
            int r0 = m0 + m_base + mt * 16 + (lane >> 2);
            int col = n0 + n_base + nf * 8 + (lane & 3) * 2;
            float2 bv = *(const float2*)&bias[col];
            float* cc = Creg[mt][nf];
            float c00 = cc[0] + bv.x, c01 = cc[1] + bv.y;
            float c10 = cc[2] + bv.x, c11 = cc[3] + bv.y;
            if (Cf == nullptr) {
                uint32_t h0 = pack_bf16(c00, c01);
                uint32_t h1 = pack_bf16(c10, c11);
                __nv_bfloat162 hh0 = *(__nv_bfloat162*)&h0;
                __nv_bfloat162 hh1 = *(__nv_bfloat162*)&h1;
                uint32_t lo0 = pack_bf16(c00 - __bfloat162float(hh0.x), c01 - __bfloat162float(hh0.y));
                uint32_t lo1 = pack_bf16(c10 - __bfloat162float(hh1.x), c11 - __bfloat162float(hh1.y));
                *(uint32_t*)&ga.ovh[(size_t)r0 * DIM + col] = h0;
                *(uint32_t*)&ga.ovl[(size_t)r0 * DIM + col] = lo0;
                *(uint32_t*)&ga.ovh[(size_t)(r0 + 8) * DIM + col] = h1;
                *(uint32_t*)&ga.ovl[(size_t)(r0 + 8) * DIM + col] = lo1;
            } else {
                *(float2*)&Cf[(size_t)r0 * DIM + col] = {c00, c01};
                *(float2*)&Cf[(size_t)(r0 + 8) * DIM + col] = {c10, c11};
            }
        }
    }
}

// ---------------- fused RMSNorm + RoPE -> bf16 hi/lo (q and k) ----------------
__global__ __launch_bounds__(256) void rmsnorm_rope_split2(
    const float* __restrict__ xq, const float* __restrict__ xk,
    const float* __restrict__ gqv, const float* __restrict__ gkv,
    __nv_bfloat16* __restrict__ qh, __nv_bfloat16* __restrict__ ql,
    __nv_bfloat16* __restrict__ kh, __nv_bfloat16* __restrict__ kl) {
    int row = blockIdx.x;
    int which = blockIdx.y;
    const float* xp = (which ? xk : xq) + (size_t)row * DIM;
    const float* g = which ? gkv : gqv;
    __nv_bfloat16* oh = which ? kh : qh;
    __nv_bfloat16* ol = which ? kl : ql;
    float outscale = which ? 1.0f : 0.08838834764831845f;
    int tid = threadIdx.x;

    float ss = 0.f;
    for (int i = tid; i < DIM; i += 256) {
        float v = xp[i];
        ss += v * v;
    }
    __shared__ float red[8];
#pragma unroll
    for (int m = 16; m; m >>= 1) ss += __shfl_xor_sync(0xffffffffu, ss, m);
    if ((tid & 31) == 0) red[tid >> 5] = ss;
    __syncthreads();
    if (tid < 8) {
        float v = red[tid];
#pragma unroll
        for (int m = 4; m; m >>= 1) v += __shfl_xor_sync(0xffu, v, m);
        if (tid == 0) red[0] = rsqrtf(v * (1.0f / DIM) + 1e-6f);
    }
    __syncthreads();
    float scale = red[0];

    for (int p = tid; p < NH * NPAIR; p += 256) {
        int head = p >> 6, j = p & 63;
        int i0 = head * HD + 2 * j;
        float2 v = *(const float2*)&xp[i0];
        float2 gv = *(const float2*)&g[i0];
        float xr = v.x * scale * gv.x;
        float xi = v.y * scale * gv.y;
        float c = g_cos[row * NPAIR + j];
        float s = g_sin[row * NPAIR + j];
        float yr = (xr * c - xi * s) * outscale;
        float yi = (xr * s + xi * c) * outscale;
        __nv_bfloat16 hr = __float2bfloat16(yr);
        __nv_bfloat16 hi = __float2bfloat16(yi);
        __nv_bfloat16 lr = __float2bfloat16(yr - __bfloat162float(hr));
        __nv_bfloat16 li = __float2bfloat16(yi - __bfloat162float(hi));
        *(__nv_bfloat162*)&oh[(size_t)row * DIM + i0] = {hr, hi};
        *(__nv_bfloat162*)&ol[(size_t)row * DIM + i0] = {lr, li};
    }
}

// ---------------- HMMA flash attention v2 ----------------
// Q fragments in registers; KV triple-buffered; PV delayed one tile so its
// MMAs overlap the softmax ALU of the next tile.
#define T_B    (64 * 272)          // 17408 B per KV operand tile
#define BUFKV  (4 * T_B)           // Kh,Kl,Vh,Vl
#define ATT_SMEM (3 * BUFKV)       // 208896 B

__global__ __launch_bounds__(256, 1) void attention_hmma(
    const __nv_bfloat16* __restrict__ Qh, const __nv_bfloat16* __restrict__ Ql,
    const __nv_bfloat16* __restrict__ Kh, const __nv_bfloat16* __restrict__ Kl,
    const __nv_bfloat16* __restrict__ Vh, const __nv_bfloat16* __restrict__ Vl,
    __nv_bfloat16* __restrict__ Oh, __nv_bfloat16* __restrict__ Ol) {
    extern __shared__ char dsm[];
    uint32_t sbase = smem_u32(dsm);

    int tid = threadIdx.x, wid = tid >> 5, lane = tid & 31;
    int qb = (int)gridDim.x - 1 - blockIdx.x;
    int h = blockIdx.y;
    int q0 = qb * 128;

    // ---- stage Q into buf0 region and pull fragments to registers ----
    {
        const __nv_bfloat16* gq[2] = {Qh, Ql};
#pragma unroll
        for (int op = 0; op < 2; op++) {
            const __nv_bfloat16* src = gq[op] + (size_t)q0 * DIM + h * HD;
            uint32_t dst = sbase + (uint32_t)op * (128 * 272);
#pragma unroll
            for (int it = 0; it < 8; it++) {
                int idx = it * 256 + tid;
                int r = idx >> 4, gg = idx & 15;
                CP_ASYNC16(dst + (uint32_t)(r * 272 + gg * 16), src + (size_t)r * DIM + gg * 8);
            }
        }
        CP_COMMIT(); CP_WAIT0();
        __syncthreads();
    }
    int a_r = wid * 16 + (lane & 7) + ((lane >> 3) & 1) * 8;
    int a_half = lane >> 4;
    uint32_t qh_f[8][4], ql_f[8][4];
#pragma unroll
    for (int ks = 0; ks < 8; ks++) {
        uint32_t aoff = (uint32_t)(a_r * 272 + (a_half + 2 * ks) * 16);
        ldsm4(qh_f[ks], sbase + aoff);
        ldsm4(ql_f[ks], sbase + 128 * 272 + aoff);
    }
    __syncthreads();

    const __nv_bfloat16* gkv[4] = {Kh, Kl, Vh, Vl};
    auto load_kv = [&](int t, int b) {
        int k0 = t * 64;
#pragma unroll
        for (int op = 0; op < 4; op++) {
            const __nv_bfloat16* src = gkv[op] + (size_t)k0 * DIM + h * HD;
            uint32_t dst = sbase + (uint32_t)b * BUFKV + (uint32_t)op * T_B;
#pragma unroll
            for (int it = 0; it < 4; it++) {
                int idx = it * 256 + tid;
                int r = idx >> 4, gg = idx & 15;
                CP_ASYNC16(dst + (uint32_t)(r * 272 + gg * 16), src + (size_t)r * DIM + gg * 8);
            }
        }
    };

    float O[16][4];
#pragma unroll
    for (int i = 0; i < 16; i++)
#pragma unroll
        for (int j = 0; j < 4; j++) O[i][j] = 0.f;
    float m0 = -1e30f, m1 = -1e30f, l0 = 0.f, l1 = 0.f;
    uint32_t PhP[4][4], PlP[4][4];

    int r0g = q0 + wid * 16 + (lane >> 2);
    int fr0 = r0g / FRAME, fr1 = (r0g + 8) / FRAME;
    int blkmin_f = q0 / FRAME;
    int fqmax = (q0 + 127) / FRAME;
    int ntile = ((fqmax + 1) * FRAME + 63) >> 6;

    int b_r = ((lane >> 4) & 1) * 8 + (lane & 7);
    int b_half = (lane >> 3) & 1;
    int v_r = (lane & 15);
    int v_c = (lane >> 4) * 8;

    load_kv(0, 0); CP_COMMIT();
    load_kv(1, 1); CP_COMMIT();

    int bc = 0, bp = 2;  // current / previous buffer index (mod 3)
    for (int t = 0; t < ntile; t++) {
        if (t == ntile - 1) CP_WAIT0(); else CP_WAIT1();
        __syncthreads();

        int k0 = t * 64;
        uint32_t base_c = sbase + (uint32_t)bc * BUFKV;
        uint32_t bKh = base_c, bKl = base_c + T_B;

        // ---- S = Q K^T (Q fragments already in registers) ----
        float S[8][4];
#pragma unroll
        for (int i = 0; i < 8; i++)
#pragma unroll
            for (int j = 0; j < 4; j++) S[i][j] = 0.f;

#pragma unroll
        for (int nb = 0; nb < 4; nb++) {
#pragma unroll
            for (int ks = 0; ks < 8; ks++) {
                uint32_t kh4[4], kl4[4];
                uint32_t boff = (uint32_t)((nb * 16 + b_r) * 272 + (b_half + 2 * ks) * 16);
                ldsm4(kh4, bKh + boff);
                ldsm4(kl4, bKl + boff);
                mma16816(S[2 * nb],     qh_f[ks], &kh4[0]);
                mma16816(S[2 * nb + 1], qh_f[ks], &kh4[2]);
                mma16816(S[2 * nb],     qh_f[ks], &kl4[0]);
                mma16816(S[2 * nb + 1], qh_f[ks], &kl4[2]);
                mma16816(S[2 * nb],     ql_f[ks], &kh4[0]);
                mma16816(S[2 * nb + 1], ql_f[ks], &kh4[2]);
            }
        }

        // ---- delayed PV: O += P(t-1) V(t-1) (overlaps softmax below) ----
        if (t > 0) {
            uint32_t base_p = sbase + (uint32_t)bp * BUFKV;
            uint32_t bVh = base_p + 2 * T_B, bVl = base_p + 3 * T_B;
#pragma unroll
            for (int j = 0; j < 4; j++) {
#pragma unroll
                for (int dp = 0; dp < 4; dp++) {
                    uint32_t vh_a[4], vh_b[4], vl_a[4], vl_b[4];
                    uint32_t voff0 = (uint32_t)((j * 16 + v_r) * 272 + ((2 * dp) * 16 + v_c) * 2);
                    uint32_t voff1 = (uint32_t)((j * 16 + v_r) * 272 + ((2 * dp + 1) * 16 + v_c) * 2);
                    ldsm4t(vh_a, bVh + voff0);
                    ldsm4t(vh_b, bVh + voff1);
                    ldsm4t(vl_a, bVl + voff0);
                    ldsm4t(vl_b, bVl + voff1);
                    float* o0 = O[4 * dp + 0];
                    float* o1 = O[4 * dp + 1];
                    float* o2 = O[4 * dp + 2];
                    float* o3 = O[4 * dp + 3];
                    mma16816(o0, PhP[j], &vh_a[0]);
                    mma16816(o1, PhP[j], &vh_a[2]);
                    mma16816(o2, PhP[j], &vh_b[0]);
                    mma16816(o3, PhP[j], &vh_b[2]);
                    mma16816(o0, PhP[j], &vl_a[0]);
                    mma16816(o1, PhP[j], &vl_a[2]);
                    mma16816(o2, PhP[j], &vl_b[0]);
                    mma16816(o3, PhP[j], &vl_b[2]);
                    mma16816(o0, PlP[j], &vh_a[0]);
                    mma16816(o1, PlP[j], &vh_a[2]);
                    mma16816(o2, PlP[j], &vh_b[0]);
                    mma16816(o3, PlP[j], &vh_b[2]);
                }
            }
        }

        // ---- mask ----
        if ((k0 + 63) / FRAME > blkmin_f) {
#pragma unroll
            for (int nf = 0; nf < 8; nf++) {
                int c = k0 + nf * 8 + 2 * (lane & 3);
                int cf0 = c / FRAME, cf1 = (c + 1) / FRAME;
                if (cf0 > fr0) S[nf][0] = -1e30f;
                if (cf1 > fr0) S[nf][1] = -1e30f;
                if (cf0 > fr1) S[nf][2] = -1e30f;
                if (cf1 > fr1) S[nf][3] = -1e30f;
            }
        }

        // ---- online softmax (overlaps PV tensor work above) ----
        float mx0 = -1e30f, mx1 = -1e30f;
#pragma unroll
        for (int nf = 0; nf < 8; nf++) {
            mx0 = fmaxf(mx0, fmaxf(S[nf][0], S[nf][1]));
            mx1 = fmaxf(mx1, fmaxf(S[nf][2], S[nf][3]));
        }
        mx0 = fmaxf(mx0, __shfl_xor_sync(0xffffffffu, mx0, 1));
        mx0 = fmaxf(mx0, __shfl_xor_sync(0xffffffffu, mx0, 2));
        mx1 = fmaxf(mx1, __shfl_xor_sync(0xffffffffu, mx1, 1));
        mx1 = fmaxf(mx1, __shfl_xor_sync(0xffffffffu, mx1, 2));
        float mn0 = fmaxf(m0, mx0), mn1 = fmaxf(m1, mx1);
        float al0 = __expf(m0 - mn0), al1 = __expf(m1 - mn1);
        m0 = mn0; m1 = mn1;
#pragma unroll
        for (int i = 0; i < 16; i++) {
            O[i][0] *= al0; O[i][1] *= al0;
            O[i][2] *= al1; O[i][3] *= al1;
        }

        float ps0 = 0.f, ps1 = 0.f;
#pragma unroll
        for (int j = 0; j < 4; j++) {
            float p00 = __expf(S[2 * j][0] - mn0);
            float p01 = __expf(S[2 * j][1] - mn0);
            float p02 = __expf(S[2 * j][2] - mn1);
            float p03 = __expf(S[2 * j][3] - mn1);
            float p10 = __expf(S[2 * j + 1][0] - mn0);
            float p11 = __expf(S[2 * j + 1][1] - mn0);
            float p12 = __expf(S[2 * j + 1][2] - mn1);
            float p13 = __expf(S[2 * j + 1][3] - mn1);
            ps0 += (p00 + p01) + (p10 + p11);
            ps1 += (p02 + p03) + (p12 + p13);
            PhP[j][0] = pack_bf16(p00, p01);
            PhP[j][1] = pack_bf16(p02, p03);
            PhP[j][2] = pack_bf16(p10, p11);
            PhP[j][3] = pack_bf16(p12, p13);
            __nv_bfloat162 h0 = *(__nv_bfloat162*)&PhP[j][0];
            __nv_bfloat162 h1 = *(__nv_bfloat162*)&PhP[j][1];
            __nv_bfloat162 h2 = *(__nv_bfloat162*)&PhP[j][2];
            __nv_bfloat162 h3 = *(__nv_bfloat162*)&PhP[j][3];
            PlP[j][0] = pack_bf16(p00 - __bfloat162float(h0.x), p01 - __bfloat162float(h0.y));
            PlP[j][1] = pack_bf16(p02 - __bfloat162float(h1.x), p03 - __bfloat162float(h1.y));
            PlP[j][2] = pack_bf16(p10 - __bfloat162float(h2.x), p11 - __bfloat162float(h2.y));
            PlP[j][3] = pack_bf16(p12 - __bfloat162float(h3.x), p13 - __bfloat162float(h3.y));
        }
        ps0 += __shfl_xor_sync(0xffffffffu, ps0, 1);
        ps0 += __shfl_xor_sync(0xffffffffu, ps0, 2);
        ps1 += __shfl_xor_sync(0xffffffffu, ps1, 1);
        ps1 += __shfl_xor_sync(0xffffffffu, ps1, 2);
        l0 = l0 * al0 + ps0;
        l1 = l1 * al1 + ps1;

        // all warps done reading V(t-1) buffer -> safe to overwrite with t+2
        __syncthreads();
        if (t + 2 < ntile) { load_kv(t + 2, bp); CP_COMMIT(); }
        bp = bc;
        bc = (bc == 2) ? 0 : bc + 1;
    }

    // ---- final PV for the last tile ----
    {
        uint32_t base_p = sbase + (uint32_t)bp * BUFKV;
        uint32_t bVh = base_p + 2 * T_B, bVl = base_p + 3 * T_B;
#pragma unroll
        for (int j = 0; j < 4; j++) {
#pragma unroll
            for (int dp = 0; dp < 4; dp++) {
                uint32_t vh_a[4], vh_b[4], vl_a[4], vl_b[4];
                uint32_t voff0 = (uint32_t)((j * 16 + v_r) * 272 + ((2 * dp) * 16 + v_c) * 2);
                uint32_t voff1 = (uint32_t)((j * 16 + v_r) * 272 + ((2 * dp + 1) * 16 + v_c) * 2);
                ldsm4t(vh_a, bVh + voff0);
                ldsm4t(vh_b, bVh + voff1);
                ldsm4t(vl_a, bVl + voff0);
                ldsm4t(vl_b, bVl + voff1);
                float* o0 = O[4 * dp + 0];
                float* o1 = O[4 * dp + 1];
                float* o2 = O[4 * dp + 2];
                float* o3 = O[4 * dp + 3];
                mma16816(o0, PhP[j], &vh_a[0]);
                mma16816(o1, PhP[j], &vh_a[2]);
                mma16816(o2, PhP[j], &vh_b[0]);
                mma16816(o3, PhP[j], &vh_b[2]);
                mma16816(o0, PhP[j], &vl_a[0]);
                mma16816(o1, PhP[j], &vl_a[2]);
                mma16816(o2, PhP[j], &vl_b[0]);
                mma16816(o3, PhP[j], &vl_b[2]);
                mma16816(o0, PlP[j], &vh_a[0]);
                mma16816(o1, PlP[j], &vh_a[2]);
                mma16816(o2, PlP[j], &vh_b[0]);
                mma16816(o3, PlP[j], &vh_b[2]);
            }
        }
    }

    // ---- epilogue: normalize, split to bf16 hi/lo, store ----
    float inv0 = 1.0f / l0, inv1 = 1.0f / l1;
    int row0 = q0 + wid * 16 + (lane >> 2);
#pragma unroll
    for (int nf = 0; nf < 16; nf++) {
        int col = h * HD + nf * 8 + 2 * (lane & 3);
        float o00 = O[nf][0] * inv0, o01 = O[nf][1] * inv0;
        float o10 = O[nf][2] * inv1, o11 = O[nf][3] * inv1;
        uint32_t h0 = pack_bf16(o00, o01);
        uint32_t h1 = pack_bf16(o10, o11);
        __nv_bfloat162 hh0 = *(__nv_bfloat162*)&h0;
        __nv_bfloat162 hh1 = *(__nv_bfloat162*)&h1;
        uint32_t lo0 = pack_bf16(o00 - __bfloat162float(hh0.x), o01 - __bfloat162float(hh0.y));
        uint32_t lo1 = pack_bf16(o10 - __bfloat162float(hh1.x), o11 - __bfloat162float(hh1.y));
        *(uint32_t*)&Oh[(size_t)row0 * DIM + col] = h0;
        *(uint32_t*)&Ol[(size_t)row0 * DIM + col] = lo0;
        *(uint32_t*)&Oh[(size_t)(row0 + 8) * DIM + col] = h1;
        *(uint32_t*)&Ol[(size_t)(row0 + 8) * DIM + col] = lo1;
    }
}

// ---------------- launch ----------------
extern "C" void kernel_launch(void* const* d_in, const int* in_sizes, int n_in,
                              void* d_out, int out_size) {
    const float* x  = (const float*)d_in[0];
    const float* Wq = (const float*)d_in[1];
    const float* bq = (const float*)d_in[2];
    const float* Wk = (const float*)d_in[3];
    const float* bk = (const float*)d_in[4];
    const float* Wv = (const float*)d_in[5];
    const float* bv = (const float*)d_in[6];
    const float* Wo = (const float*)d_in[7];
    const float* bo = (const float*)d_in[8];
    const float* gq = (const float*)d_in[9];
    const float* gk = (const float*)d_in[10];
    const float* ff = (const float*)d_in[11];
    const float* fh = (const float*)d_in[12];
    const float* fw = (const float*)d_in[13];
    float* out = (float*)d_out;

    float *qp, *kp;
    __nv_bfloat16 *ah, *al, *qh, *ql, *kh, *kl, *vh, *vl, *whb, *wlb;
    cudaGetSymbolAddress((void**)&qp, g_q);
    cudaGetSymbolAddress((void**)&kp, g_k);
    cudaGetSymbolAddress((void**)&ah, g_ah);
    cudaGetSymbolAddress((void**)&al, g_al);
    cudaGetSymbolAddress((void**)&whb, g_wh);
    cudaGetSymbolAddress((void**)&wlb, g_wl);
    cudaGetSymbolAddress((void**)&qh, g_qh);
    cudaGetSymbolAddress((void**)&ql, g_ql);
    cudaGetSymbolAddress((void**)&kh, g_kh);
    cudaGetSymbolAddress((void**)&kl, g_kl);
    cudaGetSymbolAddress((void**)&vh, g_vh);
    cudaGetSymbolAddress((void**)&vl, g_vl);

    cudaFuncSetAttribute(gemm_hmma,
                         cudaFuncAttributeMaxDynamicSharedMemorySize, GSMEM);
    cudaFuncSetAttribute(attention_hmma,
                         cudaFuncAttributeMaxDynamicSharedMemorySize, ATT_SMEM);

    angles_kernel<<<(L_TOK * NPAIR + 255) / 256, 256>>>(ff, fh, fw);

    const int NELT = L_TOK * DIM;
    split_kernel<<<(NELT / 4 + 255) / 256, 256>>>(x, ah, al, NELT);

    transpose_split4_kernel<<<dim3(DIM / 32, DIM / 32, 4), dim3(32, 8)>>>(
        Wq, Wk, Wv, Wo, whb, wlb);

    const size_t WSZ = (size_t)DIM * DIM;
    GemmArgs ga;
    ga.wh0 = whb;           ga.wl0 = wlb;           ga.b0 = bq; ga.o0 = qp;
    ga.wh1 = whb + WSZ;     ga.wl1 = wlb + WSZ;     ga.b1 = bk; ga.o1 = kp;
    ga.wh2 = whb + 2 * WSZ; ga.wl2 = wlb + 2 * WSZ; ga.b2 = bv;
    ga.ovh = vh;            ga.ovl = vl;
    gemm_hmma<<<dim3(DIM / 128, L_TOK / 128, 3), 256, GSMEM>>>(ah, al, ga);

    rmsnorm_rope_split2<<<dim3(L_TOK, 2), 256>>>(qp, kp, gq, gk, qh, ql, kh, kl);

    attention_hmma<<<dim3(30, NH), 256, ATT_SMEM>>>(qh, ql, kh, kl, vh, vl, ah, al);

    GemmArgs go;
    go.wh0 = whb + 3 * WSZ; go.wl0 = wlb + 3 * WSZ; go.b0 = bo; go.o0 = out;
    go.wh1 = go.wh0; go.wl1 = go.wl0; go.b1 = bo; go.o1 = out;
    go.wh2 = go.wh0; go.wl2 = go.wl0; go.b2 = bo;
    go.ovh = vh; go.ovl = vl;
    gemm_hmma<<<dim3(DIM / 128, L_TOK / 128, 1), 256, GSMEM>>>(ah, al, go);
}

// round 9
// speedup vs baseline: 1.0463x; 1.0463x over previous
#include <cuda_runtime.h>
#include <cuda_bf16.h>
#include <math.h>
#include <stdint.h>

#define L_TOK 3840
#define DIM   1536
#define NH    12
#define HD    128
#define FRAME 480
#define NPAIR 64

// ---------------- device scratch (no allocs allowed) ----------------
__device__ float g_q[L_TOK * DIM];
__device__ float g_k[L_TOK * DIM];
__device__ float g_cos[L_TOK * NPAIR];
__device__ float g_sin[L_TOK * NPAIR];
__device__ __nv_bfloat16 g_ah[L_TOK * DIM];      // GEMM A hi (x, later attn out)
__device__ __nv_bfloat16 g_al[L_TOK * DIM];      // GEMM A lo
__device__ __nv_bfloat16 g_wh[4][DIM * DIM];     // W^T hi  [N][K] for q,k,v,o
__device__ __nv_bfloat16 g_wl[4][DIM * DIM];     // W^T lo
__device__ __nv_bfloat16 g_qh[L_TOK * DIM];
__device__ __nv_bfloat16 g_ql[L_TOK * DIM];
__device__ __nv_bfloat16 g_kh[L_TOK * DIM];
__device__ __nv_bfloat16 g_kl[L_TOK * DIM];
__device__ __nv_bfloat16 g_vh[L_TOK * DIM];
__device__ __nv_bfloat16 g_vl[L_TOK * DIM];

// =================== sm_80-era PTX helpers (valid on plain sm_103) ==========
__device__ __forceinline__ uint32_t smem_u32(const void* p) {
    uint32_t a;
    asm("{ .reg .u64 t; cvta.to.shared.u64 t, %1; cvt.u32.u64 %0, t; }" : "=r"(a) : "l"(p));
    return a;
}
#define CP_ASYNC16(dst, src) \
    asm volatile("cp.async.cg.shared.global [%0], [%1], 16;" :: "r"(dst), "l"(src))
#define CP_COMMIT() asm volatile("cp.async.commit_group;" ::: "memory")
#define CP_WAIT1()  asm volatile("cp.async.wait_group 1;" ::: "memory")
#define CP_WAIT0()  asm volatile("cp.async.wait_group 0;" ::: "memory")

__device__ __forceinline__ void ldsm4(uint32_t* r, uint32_t addr) {
    asm volatile("ldmatrix.sync.aligned.m8n8.x4.shared.b16 {%0,%1,%2,%3}, [%4];"
                 : "=r"(r[0]), "=r"(r[1]), "=r"(r[2]), "=r"(r[3]) : "r"(addr));
}
__device__ __forceinline__ void ldsm4t(uint32_t* r, uint32_t addr) {
    asm volatile("ldmatrix.sync.aligned.m8n8.x4.trans.shared.b16 {%0,%1,%2,%3}, [%4];"
                 : "=r"(r[0]), "=r"(r[1]), "=r"(r[2]), "=r"(r[3]) : "r"(addr));
}
__device__ __forceinline__ void mma16816(float* c, const uint32_t* a, const uint32_t* b) {
    asm volatile("mma.sync.aligned.m16n8k16.row.col.f32.bf16.bf16.f32 "
                 "{%0,%1,%2,%3}, {%4,%5,%6,%7}, {%8,%9}, {%0,%1,%2,%3};"
                 : "+f"(c[0]), "+f"(c[1]), "+f"(c[2]), "+f"(c[3])
                 : "r"(a[0]), "r"(a[1]), "r"(a[2]), "r"(a[3]), "r"(b[0]), "r"(b[1]));
}
#define SWZ128(off) ((off) ^ (((off) >> 3) & 0x70))

__device__ __forceinline__ uint32_t pack_bf16(float lo, float hi) {
    uint32_t r;
    asm("cvt.rn.bf16x2.f32 %0, %1, %2;" : "=r"(r) : "f"(hi), "f"(lo));
    return r;
}

// ---------------- angle table ----------------
__global__ void angles_kernel(const float* __restrict__ ff,
                              const float* __restrict__ fh,
                              const float* __restrict__ fw) {
    int idx = blockIdx.x * blockDim.x + threadIdx.x;
    if (idx >= L_TOK * NPAIR) return;
    int l = idx / NPAIR, j = idx % NPAIR;
    int f = l / FRAME, r = l % FRAME;
    int h = r / 30, w = r % 30;
    float a;
    if (j < 22)      a = ff[f * 22 + j];
    else if (j < 43) a = fh[h * 21 + (j - 22)];
    else             a = fw[w * 21 + (j - 43)];
    g_cos[idx] = cosf(a);
    g_sin[idx] = sinf(a);
}

// ---------------- split fp32 -> bf16 hi/lo ----------------
__global__ __launch_bounds__(256) void split_kernel(const float* __restrict__ x,
                                                    __nv_bfloat16* __restrict__ hi,
                                                    __nv_bfloat16* __restrict__ lo, int n) {
    int i = blockIdx.x * blockDim.x + threadIdx.x;
    if (i * 4 >= n) return;
    float4 v = *(const float4*)&x[i * 4];
    __nv_bfloat16 h0 = __float2bfloat16(v.x), h1 = __float2bfloat16(v.y);
    __nv_bfloat16 h2 = __float2bfloat16(v.z), h3 = __float2bfloat16(v.w);
    __nv_bfloat16 l0 = __float2bfloat16(v.x - __bfloat162float(h0));
    __nv_bfloat16 l1 = __float2bfloat16(v.y - __bfloat162float(h1));
    __nv_bfloat16 l2 = __float2bfloat16(v.z - __bfloat162float(h2));
    __nv_bfloat16 l3 = __float2bfloat16(v.w - __bfloat162float(h3));
    __nv_bfloat162* ph = (__nv_bfloat162*)&hi[i * 4];
    __nv_bfloat162* pl = (__nv_bfloat162*)&lo[i * 4];
    ph[0] = {h0, h1}; ph[1] = {h2, h3};
    pl[0] = {l0, l1}; pl[1] = {l2, l3};
}

// ------- fused transpose of 4 weights [K,N] -> [N,K] with hi/lo split -------
__global__ __launch_bounds__(256) void transpose_split4_kernel(
    const float* __restrict__ W0, const float* __restrict__ W1,
    const float* __restrict__ W2, const float* __restrict__ W3,
    __nv_bfloat16* __restrict__ ThBase, __nv_bfloat16* __restrict__ TlBase) {
    __shared__ float t[32][33];
    int z = blockIdx.z;
    const float* W = (z == 0) ? W0 : (z == 1) ? W1 : (z == 2) ? W2 : W3;
    __nv_bfloat16* Th = ThBase + (size_t)z * DIM * DIM;
    __nv_bfloat16* Tl = TlBase + (size_t)z * DIM * DIM;
    int tx = threadIdx.x, ty = threadIdx.y;  // 32 x 8
    int x0 = blockIdx.x * 32, y0 = blockIdx.y * 32;
#pragma unroll
    for (int i = 0; i < 32; i += 8)
        t[ty + i][tx] = W[(size_t)(y0 + ty + i) * DIM + x0 + tx];
    __syncthreads();
#pragma unroll
    for (int i = 0; i < 32; i += 8) {
        float v = t[tx][ty + i];
        __nv_bfloat16 h = __float2bfloat16(v);
        __nv_bfloat16 l = __float2bfloat16(v - __bfloat162float(h));
        size_t o = (size_t)(x0 + ty + i) * DIM + y0 + tx;
        Th[o] = h;
        Tl[o] = l;
    }
}

// ---------------- HMMA split-bf16 GEMM (exact R6: 256t, 2-stage) ----------------
#define GK       64
#define TILE_B   16384
#define BUF_B    (4 * TILE_B)
#define GSMEM    (1024 + 2 * BUF_B)

struct GemmArgs {
    const __nv_bfloat16 *wh0, *wl0, *wh1, *wl1, *wh2, *wl2;
    const float *b0, *b1, *b2;
    float *o0, *o1;
    __nv_bfloat16 *ovh, *ovl;
};

__global__ __launch_bounds__(256, 1) void gemm_hmma(const __nv_bfloat16* __restrict__ Ah,
                                                    const __nv_bfloat16* __restrict__ Al,
                                                    GemmArgs ga) {
    extern __shared__ char dsm[];
    uint32_t raw = smem_u32(dsm);
    uint32_t sbase = (raw + 1023u) & ~1023u;

    int tid = threadIdx.x;
    int wid = tid >> 5, lane = tid & 31;
    int m0 = blockIdx.y * 128;
    int n0 = blockIdx.x * 128;

    const __nv_bfloat16 *Bh, *Bl;
    const float* bias;
    float* Cf;
    if (blockIdx.z == 0)      { Bh = ga.wh0; Bl = ga.wl0; bias = ga.b0; Cf = ga.o0; }
    else if (blockIdx.z == 1) { Bh = ga.wh1; Bl = ga.wl1; bias = ga.b1; Cf = ga.o1; }
    else                      { Bh = ga.wh2; Bl = ga.wl2; bias = ga.b2; Cf = nullptr; }

    const __nv_bfloat16* srcs[4] = {Ah, Al, Bh, Bl};
    const int rbase[4] = {m0, m0, n0, n0};

    auto load_chunk = [&](int c, int buf) {
        uint32_t dst0 = sbase + (uint32_t)buf * BUF_B;
#pragma unroll
        for (int it = 0; it < 16; it++) {
            int idx = it * 256 + tid;
            int tile = idx >> 10;
            int rem = idx & 1023;
            int r = rem >> 3, g = rem & 7;
            const __nv_bfloat16* src = srcs[tile] + (size_t)(rbase[tile] + r) * DIM + c * GK + g * 8;
            uint32_t off = (uint32_t)(r * 128 + g * 16);
            CP_ASYNC16(dst0 + (uint32_t)tile * TILE_B + SWZ128(off), src);
        }
    };

    float Creg[2][8][4];
#pragma unroll
    for (int mt = 0; mt < 2; mt++)
#pragma unroll
        for (int nf = 0; nf < 8; nf++)
#pragma unroll
            for (int j = 0; j < 4; j++) Creg[mt][nf][j] = 0.f;

    int m_base = (wid & 3) * 32;
    int n_base = (wid >> 2) * 64;
    int a_r = m_base + (lane & 7) + ((lane >> 3) & 1) * 8;
    int a_g = (lane >> 4);
    int b_r = n_base + ((lane >> 4) & 1) * 8 + (lane & 7);
    int b_g = (lane >> 3) & 1;

    const int NCH = DIM / GK;
    load_chunk(0, 0); CP_COMMIT();
    load_chunk(1, 1); CP_COMMIT();

    for (int c = 0; c < NCH; c++) {
        if (c == NCH - 1) CP_WAIT0(); else CP_WAIT1();
        __syncthreads();

        int buf = c & 1;
        uint32_t sb = sbase + (uint32_t)buf * BUF_B;
        uint32_t sAh = sb, sAl = sb + TILE_B, sBh = sb + 2 * TILE_B, sBl = sb + 3 * TILE_B;

#pragma unroll
        for (int ks = 0; ks < 4; ks++) {
            uint32_t ah[2][4], al[2][4], bh[16], bl[16];
#pragma unroll
            for (int mt = 0; mt < 2; mt++) {
                uint32_t off = SWZ128((uint32_t)((a_r + mt * 16) * 128 + (a_g + 2 * ks) * 16));
                ldsm4(ah[mt], sAh + off);
                ldsm4(al[mt], sAl + off);
            }
#pragma unroll
            for (int nf2 = 0; nf2 < 4; nf2++) {
                uint32_t off = SWZ128((uint32_t)((b_r + nf2 * 16) * 128 + (b_g + 2 * ks) * 16));
                ldsm4(&bh[nf2 * 4], sBh + off);
                ldsm4(&bl[nf2 * 4], sBl + off);
            }
#pragma unroll
            for (int nf = 0; nf < 8; nf++)
#pragma unroll
                for (int mt = 0; mt < 2; mt++)
                    mma16816(Creg[mt][nf], ah[mt], &bh[nf * 2]);
#pragma unroll
            for (int nf = 0; nf < 8; nf++)
#pragma unroll
                for (int mt = 0; mt < 2; mt++)
                    mma16816(Creg[mt][nf], ah[mt], &bl[nf * 2]);
#pragma unroll
            for (int nf = 0; nf < 8; nf++)
#pragma unroll
                for (int mt = 0; mt < 2; mt++)
                    mma16816(Creg[mt][nf], al[mt], &bh[nf * 2]);
        }
        __syncthreads();
        if (c + 2 < NCH) { load_chunk(c + 2, buf); CP_COMMIT(); }
    }

#pragma unroll
    for (int mt = 0; mt < 2; mt++) {
#pragma unroll
        for (int nf = 0; nf < 8; nf++) {
            int r0 = m0 + m_base + mt * 16 + (lane >> 2);
            int col = n0 + n_base + nf * 8 + (lane & 3) * 2;
            float2 bv = *(const float2*)&bias[col];
            float* cc = Creg[mt][nf];
            float c00 = cc[0] + bv.x, c01 = cc[1] + bv.y;
            float c10 = cc[2] + bv.x, c11 = cc[3] + bv.y;
            if (Cf == nullptr) {
                uint32_t h0 = pack_bf16(c00, c01);
                uint32_t h1 = pack_bf16(c10, c11);
                __nv_bfloat162 hh0 = *(__nv_bfloat162*)&h0;
                __nv_bfloat162 hh1 = *(__nv_bfloat162*)&h1;
                uint32_t lo0 = pack_bf16(c00 - __bfloat162float(hh0.x), c01 - __bfloat162float(hh0.y));
                uint32_t lo1 = pack_bf16(c10 - __bfloat162float(hh1.x), c11 - __bfloat162float(hh1.y));
                *(uint32_t*)&ga.ovh[(size_t)r0 * DIM + col] = h0;
                *(uint32_t*)&ga.ovl[(size_t)r0 * DIM + col] = lo0;
                *(uint32_t*)&ga.ovh[(size_t)(r0 + 8) * DIM + col] = h1;
                *(uint32_t*)&ga.ovl[(size_t)(r0 + 8) * DIM + col] = lo1;
            } else {
                *(float2*)&Cf[(size_t)r0 * DIM + col] = {c00, c01};
                *(float2*)&Cf[(size_t)(r0 + 8) * DIM + col] = {c10, c11};
            }
        }
    }
}

// ---------------- fused RMSNorm + RoPE -> bf16 hi/lo (q and k) ----------------
__global__ __launch_bounds__(256) void rmsnorm_rope_split2(
    const float* __restrict__ xq, const float* __restrict__ xk,
    const float* __restrict__ gqv, const float* __restrict__ gkv,
    __nv_bfloat16* __restrict__ qh, __nv_bfloat16* __restrict__ ql,
    __nv_bfloat16* __restrict__ kh, __nv_bfloat16* __restrict__ kl) {
    int row = blockIdx.x;
    int which = blockIdx.y;
    const float* xp = (which ? xk : xq) + (size_t)row * DIM;
    const float* g = which ? gkv : gqv;
    __nv_bfloat16* oh = which ? kh : qh;
    __nv_bfloat16* ol = which ? kl : ql;
    float outscale = which ? 1.0f : 0.08838834764831845f;
    int tid = threadIdx.x;

    float ss = 0.f;
    for (int i = tid; i < DIM; i += 256) {
        float v = xp[i];
        ss += v * v;
    }
    __shared__ float red[8];
#pragma unroll
    for (int m = 16; m; m >>= 1) ss += __shfl_xor_sync(0xffffffffu, ss, m);
    if ((tid & 31) == 0) red[tid >> 5] = ss;
    __syncthreads();
    if (tid < 8) {
        float v = red[tid];
#pragma unroll
        for (int m = 4; m; m >>= 1) v += __shfl_xor_sync(0xffu, v, m);
        if (tid == 0) red[0] = rsqrtf(v * (1.0f / DIM) + 1e-6f);
    }
    __syncthreads();
    float scale = red[0];

    for (int p = tid; p < NH * NPAIR; p += 256) {
        int head = p >> 6, j = p & 63;
        int i0 = head * HD + 2 * j;
        float2 v = *(const float2*)&xp[i0];
        float2 gv = *(const float2*)&g[i0];
        float xr = v.x * scale * gv.x;
        float xi = v.y * scale * gv.y;
        float c = g_cos[row * NPAIR + j];
        float s = g_sin[row * NPAIR + j];
        float yr = (xr * c - xi * s) * outscale;
        float yi = (xr * s + xi * c) * outscale;
        __nv_bfloat16 hr = __float2bfloat16(yr);
        __nv_bfloat16 hi = __float2bfloat16(yi);
        __nv_bfloat16 lr = __float2bfloat16(yr - __bfloat162float(hr));
        __nv_bfloat16 li = __float2bfloat16(yi - __bfloat162float(hi));
        *(__nv_bfloat162*)&oh[(size_t)row * DIM + i0] = {hr, hi};
        *(__nv_bfloat162*)&ol[(size_t)row * DIM + i0] = {lr, li};
    }
}

// ---------------- HMMA flash attention v3: delayed PV, asymmetric rings -----
// Smem layout (all tiles = two 128B-row SW128 subtiles, no padding):
//   Qh [0,32768)  Ql [32768,65536)         (128 rows; subtile=16384B)
//   K ring (2 bufs of 32768 = Kh(16384)+Kl) at 65536
//   V ring (3 bufs of 32768 = Vh+Vl)       at 131072
#define ATT_Q    0
#define ATT_K    65536
#define ATT_V    131072
#define ATT_SMEM 229376

__global__ __launch_bounds__(256, 1) void attention_hmma(
    const __nv_bfloat16* __restrict__ Qh, const __nv_bfloat16* __restrict__ Ql,
    const __nv_bfloat16* __restrict__ Kh, const __nv_bfloat16* __restrict__ Kl,
    const __nv_bfloat16* __restrict__ Vh, const __nv_bfloat16* __restrict__ Vl,
    __nv_bfloat16* __restrict__ Oh, __nv_bfloat16* __restrict__ Ol) {
    extern __shared__ char dsm[];
    uint32_t sbase = smem_u32(dsm);

    int tid = threadIdx.x, wid = tid >> 5, lane = tid & 31;
    int qb = (int)gridDim.x - 1 - blockIdx.x;
    int h = blockIdx.y;
    int q0 = qb * 128;

    // ---- load Q (subtile layout: granule gg: sub=gg>>3, col16=gg&7) ----
    {
        const __nv_bfloat16* gq[2] = {Qh, Ql};
#pragma unroll
        for (int op = 0; op < 2; op++) {
            const __nv_bfloat16* src = gq[op] + (size_t)q0 * DIM + h * HD;
            uint32_t dst = sbase + ATT_Q + (uint32_t)op * 32768;
#pragma unroll
            for (int it = 0; it < 8; it++) {
                int idx = it * 256 + tid;
                int r = idx >> 4, gg = idx & 15;
                uint32_t off = (uint32_t)((gg >> 3) * 16384) + SWZ128((uint32_t)(r * 128 + (gg & 7) * 16));
                CP_ASYNC16(dst + off, src + (size_t)r * DIM + gg * 8);
            }
        }
        CP_COMMIT();
    }

    const __nv_bfloat16* gkv[4] = {Kh, Kl, Vh, Vl};
    auto load_kv = [&](int t) {
        int k0 = t * 64;
        uint32_t kb = sbase + ATT_K + (uint32_t)(t & 1) * 32768;
        uint32_t vb = sbase + ATT_V + (uint32_t)(t % 3) * 32768;
        uint32_t dsts[4] = {kb, kb + 16384, vb, vb + 16384};
#pragma unroll
        for (int op = 0; op < 4; op++) {
            const __nv_bfloat16* src = gkv[op] + (size_t)k0 * DIM + h * HD;
#pragma unroll
            for (int it = 0; it < 4; it++) {
                int idx = it * 256 + tid;
                int r = idx >> 4, gg = idx & 15;
                uint32_t off = (uint32_t)((gg >> 3) * 8192) + SWZ128((uint32_t)(r * 128 + (gg & 7) * 16));
                CP_ASYNC16(dsts[op] + off, src + (size_t)r * DIM + gg * 8);
            }
        }
    };

    float O[16][4];
#pragma unroll
    for (int i = 0; i < 16; i++)
#pragma unroll
        for (int j = 0; j < 4; j++) O[i][j] = 0.f;
    float m0 = -1e30f, m1 = -1e30f, l0 = 0.f, l1 = 0.f;
    uint32_t PhP[4][4], PlP[4][4];

    int r0g = q0 + wid * 16 + (lane >> 2);
    int fr0 = r0g / FRAME, fr1 = (r0g + 8) / FRAME;
    int blkmin_f = q0 / FRAME;
    int fqmax = (q0 + 127) / FRAME;
    int ntile = ((fqmax + 1) * FRAME + 63) >> 6;

    int a_r = wid * 16 + (lane & 7) + ((lane >> 3) & 1) * 8;
    int a_half = lane >> 4;
    int b_r = ((lane >> 4) & 1) * 8 + (lane & 7);
    int b_half = (lane >> 3) & 1;
    int v_r = (lane & 15);
    int vg = (lane >> 4);

    load_kv(0); CP_COMMIT();
    load_kv(1); CP_COMMIT();

    for (int t = 0; t < ntile; t++) {
        if (t == ntile - 1) CP_WAIT0(); else CP_WAIT1();
        __syncthreads();

        int k0 = t * 64;
        uint32_t kb = sbase + ATT_K + (uint32_t)(t & 1) * 32768;
        uint32_t bKh = kb, bKl = kb + 16384;

        // ---- S = Q K^T ----
        float S[8][4];
#pragma unroll
        for (int i = 0; i < 8; i++)
#pragma unroll
            for (int j = 0; j < 4; j++) S[i][j] = 0.f;

#pragma unroll
        for (int ks = 0; ks < 8; ks++) {
            uint32_t qa[4], ql4[4], kh4[16], kl4[16];
            uint32_t gq16 = (uint32_t)(((ks & 3) * 2 + a_half) * 16);
            uint32_t aoff = (uint32_t)((ks >> 2) * 16384) + SWZ128((uint32_t)(a_r * 128) + gq16);
            ldsm4(qa, sbase + ATT_Q + aoff);
            ldsm4(ql4, sbase + ATT_Q + 32768 + aoff);
            uint32_t gk16 = (uint32_t)(((ks & 3) * 2 + b_half) * 16);
#pragma unroll
            for (int nb = 0; nb < 4; nb++) {
                uint32_t boff = (uint32_t)((ks >> 2) * 8192) +
                                SWZ128((uint32_t)((nb * 16 + b_r) * 128) + gk16);
                ldsm4(&kh4[nb * 4], bKh + boff);
                ldsm4(&kl4[nb * 4], bKl + boff);
            }
#pragma unroll
            for (int nf = 0; nf < 8; nf++) mma16816(S[nf], qa, &kh4[nf * 2]);
#pragma unroll
            for (int nf = 0; nf < 8; nf++) mma16816(S[nf], qa, &kl4[nf * 2]);
#pragma unroll
            for (int nf = 0; nf < 8; nf++) mma16816(S[nf], ql4, &kh4[nf * 2]);
        }

        // ---- delayed PV: O += P(t-1) V(t-1)  (overlaps softmax below) ----
        if (t > 0) {
            uint32_t vb = sbase + ATT_V + (uint32_t)((t - 1) % 3) * 32768;
            uint32_t bVh = vb, bVl = vb + 16384;
#pragma unroll
            for (int j = 0; j < 4; j++) {
#pragma unroll
                for (int dp = 0; dp < 4; dp++) {
                    int db0 = 2 * dp, db1 = 2 * dp + 1;
                    uint32_t row = (uint32_t)((j * 16 + v_r) * 128);
                    uint32_t voff0 = (uint32_t)((db0 >> 2) * 8192) +
                                     SWZ128(row + (uint32_t)(((db0 & 3) * 2 + vg) * 16));
                    uint32_t voff1 = (uint32_t)((db1 >> 2) * 8192) +
                                     SWZ128(row + (uint32_t)(((db1 & 3) * 2 + vg) * 16));
                    uint32_t vh_a[4], vh_b[4], vl_a[4], vl_b[4];
                    ldsm4t(vh_a, bVh + voff0);
                    ldsm4t(vh_b, bVh + voff1);
                    ldsm4t(vl_a, bVl + voff0);
                    ldsm4t(vl_b, bVl + voff1);
                    float* o0 = O[4 * dp + 0];
                    float* o1 = O[4 * dp + 1];
                    float* o2 = O[4 * dp + 2];
                    float* o3 = O[4 * dp + 3];
                    mma16816(o0, PhP[j], &vh_a[0]);
                    mma16816(o1, PhP[j], &vh_a[2]);
                    mma16816(o2, PhP[j], &vh_b[0]);
                    mma16816(o3, PhP[j], &vh_b[2]);
                    mma16816(o0, PhP[j], &vl_a[0]);
                    mma16816(o1, PhP[j], &vl_a[2]);
                    mma16816(o2, PhP[j], &vl_b[0]);
                    mma16816(o3, PhP[j], &vl_b[2]);
                    mma16816(o0, PlP[j], &vh_a[0]);
                    mma16816(o1, PlP[j], &vh_a[2]);
                    mma16816(o2, PlP[j], &vh_b[0]);
                    mma16816(o3, PlP[j], &vh_b[2]);
                }
            }
        }

        // ---- mask ----
        if ((k0 + 63) / FRAME > blkmin_f) {
#pragma unroll
            for (int nf = 0; nf < 8; nf++) {
                int c = k0 + nf * 8 + 2 * (lane & 3);
                int cf0 = c / FRAME, cf1 = (c + 1) / FRAME;
                if (cf0 > fr0) S[nf][0] = -1e30f;
                if (cf1 > fr0) S[nf][1] = -1e30f;
                if (cf0 > fr1) S[nf][2] = -1e30f;
                if (cf1 > fr1) S[nf][3] = -1e30f;
            }
        }

        // ---- online softmax ----
        float mx0 = -1e30f, mx1 = -1e30f;
#pragma unroll
        for (int nf = 0; nf < 8; nf++) {
            mx0 = fmaxf(mx0, fmaxf(S[nf][0], S[nf][1]));
            mx1 = fmaxf(mx1, fmaxf(S[nf][2], S[nf][3]));
        }
        mx0 = fmaxf(mx0, __shfl_xor_sync(0xffffffffu, mx0, 1));
        mx0 = fmaxf(mx0, __shfl_xor_sync(0xffffffffu, mx0, 2));
        mx1 = fmaxf(mx1, __shfl_xor_sync(0xffffffffu, mx1, 1));
        mx1 = fmaxf(mx1, __shfl_xor_sync(0xffffffffu, mx1, 2));
        float mn0 = fmaxf(m0, mx0), mn1 = fmaxf(m1, mx1);
        float al0 = __expf(m0 - mn0), al1 = __expf(m1 - mn1);
        m0 = mn0; m1 = mn1;
#pragma unroll
        for (int i = 0; i < 16; i++) {
            O[i][0] *= al0; O[i][1] *= al0;
            O[i][2] *= al1; O[i][3] *= al1;
        }

        float ps0 = 0.f, ps1 = 0.f;
#pragma unroll
        for (int j = 0; j < 4; j++) {
            float p00 = __expf(S[2 * j][0] - mn0);
            float p01 = __expf(S[2 * j][1] - mn0);
            float p02 = __expf(S[2 * j][2] - mn1);
            float p03 = __expf(S[2 * j][3] - mn1);
            float p10 = __expf(S[2 * j + 1][0] - mn0);
            float p11 = __expf(S[2 * j + 1][1] - mn0);
            float p12 = __expf(S[2 * j + 1][2] - mn1);
            float p13 = __expf(S[2 * j + 1][3] - mn1);
            ps0 += (p00 + p01) + (p10 + p11);
            ps1 += (p02 + p03) + (p12 + p13);
            PhP[j][0] = pack_bf16(p00, p01);
            PhP[j][1] = pack_bf16(p02, p03);
            PhP[j][2] = pack_bf16(p10, p11);
            PhP[j][3] = pack_bf16(p12, p13);
            __nv_bfloat162 h0 = *(__nv_bfloat162*)&PhP[j][0];
            __nv_bfloat162 h1 = *(__nv_bfloat162*)&PhP[j][1];
            __nv_bfloat162 h2 = *(__nv_bfloat162*)&PhP[j][2];
            __nv_bfloat162 h3 = *(__nv_bfloat162*)&PhP[j][3];
            PlP[j][0] = pack_bf16(p00 - __bfloat162float(h0.x), p01 - __bfloat162float(h0.y));
            PlP[j][1] = pack_bf16(p02 - __bfloat162float(h1.x), p03 - __bfloat162float(h1.y));
            PlP[j][2] = pack_bf16(p10 - __bfloat162float(h2.x), p11 - __bfloat162float(h2.y));
            PlP[j][3] = pack_bf16(p12 - __bfloat162float(h3.x), p13 - __bfloat162float(h3.y));
        }
        ps0 += __shfl_xor_sync(0xffffffffu, ps0, 1);
        ps0 += __shfl_xor_sync(0xffffffffu, ps0, 2);
        ps1 += __shfl_xor_sync(0xffffffffu, ps1, 1);
        ps1 += __shfl_xor_sync(0xffffffffu, ps1, 2);
        l0 = l0 * al0 + ps0;
        l1 = l1 * al1 + ps1;

        // K(t) fully read; V(t-1) fully consumed -> their slots can be refilled
        __syncthreads();
        if (t + 2 < ntile) { load_kv(t + 2); CP_COMMIT(); }
    }

    // ---- final PV for the last tile ----
    {
        uint32_t vb = sbase + ATT_V + (uint32_t)((ntile - 1) % 3) * 32768;
        uint32_t bVh = vb, bVl = vb + 16384;
#pragma unroll
        for (int j = 0; j < 4; j++) {
#pragma unroll
            for (int dp = 0; dp < 4; dp++) {
                int db0 = 2 * dp, db1 = 2 * dp + 1;
                uint32_t row = (uint32_t)((j * 16 + v_r) * 128);
                uint32_t voff0 = (uint32_t)((db0 >> 2) * 8192) +
                                 SWZ128(row + (uint32_t)(((db0 & 3) * 2 + vg) * 16));
                uint32_t voff1 = (uint32_t)((db1 >> 2) * 8192) +
                                 SWZ128(row + (uint32_t)(((db1 & 3) * 2 + vg) * 16));
                uint32_t vh_a[4], vh_b[4], vl_a[4], vl_b[4];
                ldsm4t(vh_a, bVh + voff0);
                ldsm4t(vh_b, bVh + voff1);
                ldsm4t(vl_a, bVl + voff0);
                ldsm4t(vl_b, bVl + voff1);
                float* o0 = O[4 * dp + 0];
                float* o1 = O[4 * dp + 1];
                float* o2 = O[4 * dp + 2];
                float* o3 = O[4 * dp + 3];
                mma16816(o0, PhP[j], &vh_a[0]);
                mma16816(o1, PhP[j], &vh_a[2]);
                mma16816(o2, PhP[j], &vh_b[0]);
                mma16816(o3, PhP[j], &vh_b[2]);
                mma16816(o0, PhP[j], &vl_a[0]);
                mma16816(o1, PhP[j], &vl_a[2]);
                mma16816(o2, PhP[j], &vl_b[0]);
                mma16816(o3, PhP[j], &vl_b[2]);
                mma16816(o0, PlP[j], &vh_a[0]);
                mma16816(o1, PlP[j], &vh_a[2]);
                mma16816(o2, PlP[j], &vh_b[0]);
                mma16816(o3, PlP[j], &vh_b[2]);
            }
        }
    }

    // ---- epilogue: normalize, split to bf16 hi/lo, store ----
    float inv0 = 1.0f / l0, inv1 = 1.0f / l1;
    int row0 = q0 + wid * 16 + (lane >> 2);
#pragma unroll
    for (int nf = 0; nf < 16; nf++) {
        int col = h * HD + nf * 8 + 2 * (lane & 3);
        float o00 = O[nf][0] * inv0, o01 = O[nf][1] * inv0;
        float o10 = O[nf][2] * inv1, o11 = O[nf][3] * inv1;
        uint32_t h0 = pack_bf16(o00, o01);
        uint32_t h1 = pack_bf16(o10, o11);
        __nv_bfloat162 hh0 = *(__nv_bfloat162*)&h0;
        __nv_bfloat162 hh1 = *(__nv_bfloat162*)&h1;
        uint32_t lo0 = pack_bf16(o00 - __bfloat162float(hh0.x), o01 - __bfloat162float(hh0.y));
        uint32_t lo1 = pack_bf16(o10 - __bfloat162float(hh1.x), o11 - __bfloat162float(hh1.y));
        *(uint32_t*)&Oh[(size_t)row0 * DIM + col] = h0;
        *(uint32_t*)&Ol[(size_t)row0 * DIM + col] = lo0;
        *(uint32_t*)&Oh[(size_t)(row0 + 8) * DIM + col] = h1;
        *(uint32_t*)&Ol[(size_t)(row0 + 8) * DIM + col] = lo1;
    }
}

// ---------------- launch ----------------
extern "C" void kernel_launch(void* const* d_in, const int* in_sizes, int n_in,
                              void* d_out, int out_size) {
    const float* x  = (const float*)d_in[0];
    const float* Wq = (const float*)d_in[1];
    const float* bq = (const float*)d_in[2];
    const float* Wk = (const float*)d_in[3];
    const float* bk = (const float*)d_in[4];
    const float* Wv = (const float*)d_in[5];
    const float* bv = (const float*)d_in[6];
    const float* Wo = (const float*)d_in[7];
    const float* bo = (const float*)d_in[8];
    const float* gq = (const float*)d_in[9];
    const float* gk = (const float*)d_in[10];
    const float* ff = (const float*)d_in[11];
    const float* fh = (const float*)d_in[12];
    const float* fw = (const float*)d_in[13];
    float* out = (float*)d_out;

    float *qp, *kp;
    __nv_bfloat16 *ah, *al, *qh, *ql, *kh, *kl, *vh, *vl, *whb, *wlb;
    cudaGetSymbolAddress((void**)&qp, g_q);
    cudaGetSymbolAddress((void**)&kp, g_k);
    cudaGetSymbolAddress((void**)&ah, g_ah);
    cudaGetSymbolAddress((void**)&al, g_al);
    cudaGetSymbolAddress((void**)&whb, g_wh);
    cudaGetSymbolAddress((void**)&wlb, g_wl);
    cudaGetSymbolAddress((void**)&qh, g_qh);
    cudaGetSymbolAddress((void**)&ql, g_ql);
    cudaGetSymbolAddress((void**)&kh, g_kh);
    cudaGetSymbolAddress((void**)&kl, g_kl);
    cudaGetSymbolAddress((void**)&vh, g_vh);
    cudaGetSymbolAddress((void**)&vl, g_vl);

    cudaFuncSetAttribute(gemm_hmma,
                         cudaFuncAttributeMaxDynamicSharedMemorySize, GSMEM);
    cudaFuncSetAttribute(attention_hmma,
                         cudaFuncAttributeMaxDynamicSharedMemorySize, ATT_SMEM);

    angles_kernel<<<(L_TOK * NPAIR + 255) / 256, 256>>>(ff, fh, fw);

    const int NELT = L_TOK * DIM;
    split_kernel<<<(NELT / 4 + 255) / 256, 256>>>(x, ah, al, NELT);

    transpose_split4_kernel<<<dim3(DIM / 32, DIM / 32, 4), dim3(32, 8)>>>(
        Wq, Wk, Wv, Wo, whb, wlb);

    const size_t WSZ = (size_t)DIM * DIM;
    GemmArgs ga;
    ga.wh0 = whb;           ga.wl0 = wlb;           ga.b0 = bq; ga.o0 = qp;
    ga.wh1 = whb + WSZ;     ga.wl1 = wlb + WSZ;     ga.b1 = bk; ga.o1 = kp;
    ga.wh2 = whb + 2 * WSZ; ga.wl2 = wlb + 2 * WSZ; ga.b2 = bv;
    ga.ovh = vh;            ga.ovl = vl;
    gemm_hmma<<<dim3(DIM / 128, L_TOK / 128, 3), 256, GSMEM>>>(ah, al, ga);

    rmsnorm_rope_split2<<<dim3(L_TOK, 2), 256>>>(qp, kp, gq, gk, qh, ql, kh, kl);

    attention_hmma<<<dim3(30, NH), 256, ATT_SMEM>>>(qh, ql, kh, kl, vh, vl, ah, al);

    GemmArgs go;
    go.wh0 = whb + 3 * WSZ; go.wl0 = wlb + 3 * WSZ; go.b0 = bo; go.o0 = out;
    go.wh1 = go.wh0; go.wl1 = go.wl0; go.b1 = bo; go.o1 = out;
    go.wh2 = go.wh0; go.wl2 = go.wl0; go.b2 = bo;
    go.ovh = vh; go.ovl = vl;
    gemm_hmma<<<dim3(DIM / 128, L_TOK / 128, 1), 256, GSMEM>>>(ah, al, go);
}

// round 10
// speedup vs baseline: 1.1566x; 1.1054x over previous
#include <cuda_runtime.h>
#include <cuda_bf16.h>
#include <math.h>
#include <stdint.h>

#define L_TOK 3840
#define DIM   1536
#define NH    12
#define HD    128
#define FRAME 480
#define NPAIR 64
#define N_QB  30
#define N_ITEM (N_QB * NH)

// ---------------- device scratch (no allocs allowed) ----------------
__device__ float g_q[L_TOK * DIM];
__device__ float g_k[L_TOK * DIM];
__device__ float g_cos[L_TOK * NPAIR];
__device__ float g_sin[L_TOK * NPAIR];
__device__ int   g_work;                         // persistent-attention work counter
__device__ __nv_bfloat16 g_ah[L_TOK * DIM];      // GEMM A hi (x, later attn out)
__device__ __nv_bfloat16 g_al[L_TOK * DIM];      // GEMM A lo
__device__ __nv_bfloat16 g_wh[4][DIM * DIM];     // W^T hi  [N][K] for q,k,v,o
__device__ __nv_bfloat16 g_wl[4][DIM * DIM];     // W^T lo
__device__ __nv_bfloat16 g_qh[L_TOK * DIM];
__device__ __nv_bfloat16 g_ql[L_TOK * DIM];
__device__ __nv_bfloat16 g_kh[L_TOK * DIM];
__device__ __nv_bfloat16 g_kl[L_TOK * DIM];
__device__ __nv_bfloat16 g_vh[L_TOK * DIM];
__device__ __nv_bfloat16 g_vl[L_TOK * DIM];

// =================== sm_80-era PTX helpers (valid on plain sm_103) ==========
__device__ __forceinline__ uint32_t smem_u32(const void* p) {
    uint32_t a;
    asm("{ .reg .u64 t; cvta.to.shared.u64 t, %1; cvt.u32.u64 %0, t; }" : "=r"(a) : "l"(p));
    return a;
}
#define CP_ASYNC16(dst, src) \
    asm volatile("cp.async.cg.shared.global [%0], [%1], 16;" :: "r"(dst), "l"(src))
#define CP_COMMIT() asm volatile("cp.async.commit_group;" ::: "memory")
#define CP_WAIT1()  asm volatile("cp.async.wait_group 1;" ::: "memory")
#define CP_WAIT0()  asm volatile("cp.async.wait_group 0;" ::: "memory")

__device__ __forceinline__ void ldsm4(uint32_t* r, uint32_t addr) {
    asm volatile("ldmatrix.sync.aligned.m8n8.x4.shared.b16 {%0,%1,%2,%3}, [%4];"
                 : "=r"(r[0]), "=r"(r[1]), "=r"(r[2]), "=r"(r[3]) : "r"(addr));
}
__device__ __forceinline__ void ldsm4t(uint32_t* r, uint32_t addr) {
    asm volatile("ldmatrix.sync.aligned.m8n8.x4.trans.shared.b16 {%0,%1,%2,%3}, [%4];"
                 : "=r"(r[0]), "=r"(r[1]), "=r"(r[2]), "=r"(r[3]) : "r"(addr));
}
__device__ __forceinline__ void mma16816(float* c, const uint32_t* a, const uint32_t* b) {
    asm volatile("mma.sync.aligned.m16n8k16.row.col.f32.bf16.bf16.f32 "
                 "{%0,%1,%2,%3}, {%4,%5,%6,%7}, {%8,%9}, {%0,%1,%2,%3};"
                 : "+f"(c[0]), "+f"(c[1]), "+f"(c[2]), "+f"(c[3])
                 : "r"(a[0]), "r"(a[1]), "r"(a[2]), "r"(a[3]), "r"(b[0]), "r"(b[1]));
}
#define SWZ128(off) ((off) ^ (((off) >> 3) & 0x70))

__device__ __forceinline__ uint32_t pack_bf16(float lo, float hi) {
    uint32_t r;
    asm("cvt.rn.bf16x2.f32 %0, %1, %2;" : "=r"(r) : "f"(hi), "f"(lo));
    return r;
}

// ---------------- angle table ----------------
__global__ void angles_kernel(const float* __restrict__ ff,
                              const float* __restrict__ fh,
                              const float* __restrict__ fw) {
    int idx = blockIdx.x * blockDim.x + threadIdx.x;
    if (idx >= L_TOK * NPAIR) return;
    int l = idx / NPAIR, j = idx % NPAIR;
    int f = l / FRAME, r = l % FRAME;
    int h = r / 30, w = r % 30;
    float a;
    if (j < 22)      a = ff[f * 22 + j];
    else if (j < 43) a = fh[h * 21 + (j - 22)];
    else             a = fw[w * 21 + (j - 43)];
    g_cos[idx] = cosf(a);
    g_sin[idx] = sinf(a);
}

// ---------------- split fp32 -> bf16 hi/lo ----------------
__global__ __launch_bounds__(256) void split_kernel(const float* __restrict__ x,
                                                    __nv_bfloat16* __restrict__ hi,
                                                    __nv_bfloat16* __restrict__ lo, int n) {
    int i = blockIdx.x * blockDim.x + threadIdx.x;
    if (i * 4 >= n) return;
    float4 v = *(const float4*)&x[i * 4];
    __nv_bfloat16 h0 = __float2bfloat16(v.x), h1 = __float2bfloat16(v.y);
    __nv_bfloat16 h2 = __float2bfloat16(v.z), h3 = __float2bfloat16(v.w);
    __nv_bfloat16 l0 = __float2bfloat16(v.x - __bfloat162float(h0));
    __nv_bfloat16 l1 = __float2bfloat16(v.y - __bfloat162float(h1));
    __nv_bfloat16 l2 = __float2bfloat16(v.z - __bfloat162float(h2));
    __nv_bfloat16 l3 = __float2bfloat16(v.w - __bfloat162float(h3));
    __nv_bfloat162* ph = (__nv_bfloat162*)&hi[i * 4];
    __nv_bfloat162* pl = (__nv_bfloat162*)&lo[i * 4];
    ph[0] = {h0, h1}; ph[1] = {h2, h3};
    pl[0] = {l0, l1}; pl[1] = {l2, l3};
}

// ------- fused transpose of 4 weights [K,N] -> [N,K] with hi/lo split -------
__global__ __launch_bounds__(256) void transpose_split4_kernel(
    const float* __restrict__ W0, const float* __restrict__ W1,
    const float* __restrict__ W2, const float* __restrict__ W3,
    __nv_bfloat16* __restrict__ ThBase, __nv_bfloat16* __restrict__ TlBase) {
    __shared__ float t[32][33];
    int z = blockIdx.z;
    const float* W = (z == 0) ? W0 : (z == 1) ? W1 : (z == 2) ? W2 : W3;
    __nv_bfloat16* Th = ThBase + (size_t)z * DIM * DIM;
    __nv_bfloat16* Tl = TlBase + (size_t)z * DIM * DIM;
    int tx = threadIdx.x, ty = threadIdx.y;  // 32 x 8
    int x0 = blockIdx.x * 32, y0 = blockIdx.y * 32;
#pragma unroll
    for (int i = 0; i < 32; i += 8)
        t[ty + i][tx] = W[(size_t)(y0 + ty + i) * DIM + x0 + tx];
    __syncthreads();
#pragma unroll
    for (int i = 0; i < 32; i += 8) {
        float v = t[tx][ty + i];
        __nv_bfloat16 h = __float2bfloat16(v);
        __nv_bfloat16 l = __float2bfloat16(v - __bfloat162float(h));
        size_t o = (size_t)(x0 + ty + i) * DIM + y0 + tx;
        Th[o] = h;
        Tl[o] = l;
    }
}

// ---------------- HMMA split-bf16 GEMM (R6-best: 256t, 2-stage) ----------------
#define GK       64
#define TILE_B   16384
#define BUF_B    (4 * TILE_B)
#define GSMEM    (1024 + 2 * BUF_B)

struct GemmArgs {
    const __nv_bfloat16 *wh0, *wl0, *wh1, *wl1, *wh2, *wl2;
    const float *b0, *b1, *b2;
    float *o0, *o1;
    __nv_bfloat16 *ovh, *ovl;
};

__global__ __launch_bounds__(256, 1) void gemm_hmma(const __nv_bfloat16* __restrict__ Ah,
                                                    const __nv_bfloat16* __restrict__ Al,
                                                    GemmArgs ga) {
    extern __shared__ char dsm[];
    uint32_t raw = smem_u32(dsm);
    uint32_t sbase = (raw + 1023u) & ~1023u;

    int tid = threadIdx.x;
    int wid = tid >> 5, lane = tid & 31;
    int m0 = blockIdx.y * 128;
    int n0 = blockIdx.x * 128;

    const __nv_bfloat16 *Bh, *Bl;
    const float* bias;
    float* Cf;
    if (blockIdx.z == 0)      { Bh = ga.wh0; Bl = ga.wl0; bias = ga.b0; Cf = ga.o0; }
    else if (blockIdx.z == 1) { Bh = ga.wh1; Bl = ga.wl1; bias = ga.b1; Cf = ga.o1; }
    else                      { Bh = ga.wh2; Bl = ga.wl2; bias = ga.b2; Cf = nullptr; }

    const __nv_bfloat16* srcs[4] = {Ah, Al, Bh, Bl};
    const int rbase[4] = {m0, m0, n0, n0};

    auto load_chunk = [&](int c, int buf) {
        uint32_t dst0 = sbase + (uint32_t)buf * BUF_B;
#pragma unroll
        for (int it = 0; it < 16; it++) {
            int idx = it * 256 + tid;
            int tile = idx >> 10;
            int rem = idx & 1023;
            int r = rem >> 3, g = rem & 7;
            const __nv_bfloat16* src = srcs[tile] + (size_t)(rbase[tile] + r) * DIM + c * GK + g * 8;
            uint32_t off = (uint32_t)(r * 128 + g * 16);
            CP_ASYNC16(dst0 + (uint32_t)tile * TILE_B + SWZ128(off), src);
        }
    };

    float Creg[2][8][4];
#pragma unroll
    for (int mt = 0; mt < 2; mt++)
#pragma unroll
        for (int nf = 0; nf < 8; nf++)
#pragma unroll
            for (int j = 0; j < 4; j++) Creg[mt][nf][j] = 0.f;

    int m_base = (wid & 3) * 32;
    int n_base = (wid >> 2) * 64;
    int a_r = m_base + (lane & 7) + ((lane >> 3) & 1) * 8;
    int a_g = (lane >> 4);
    int b_r = n_base + ((lane >> 4) & 1) * 8 + (lane & 7);
    int b_g = (lane >> 3) & 1;

    const int NCH = DIM / GK;
    load_chunk(0, 0); CP_COMMIT();
    load_chunk(1, 1); CP_COMMIT();

    for (int c = 0; c < NCH; c++) {
        if (c == NCH - 1) CP_WAIT0(); else CP_WAIT1();
        __syncthreads();

        int buf = c & 1;
        uint32_t sb = sbase + (uint32_t)buf * BUF_B;
        uint32_t sAh = sb, sAl = sb + TILE_B, sBh = sb + 2 * TILE_B, sBl = sb + 3 * TILE_B;

#pragma unroll
        for (int ks = 0; ks < 4; ks++) {
            uint32_t ah[2][4], al[2][4], bh[16], bl[16];
#pragma unroll
            for (int mt = 0; mt < 2; mt++) {
                uint32_t off = SWZ128((uint32_t)((a_r + mt * 16) * 128 + (a_g + 2 * ks) * 16));
                ldsm4(ah[mt], sAh + off);
                ldsm4(al[mt], sAl + off);
            }
#pragma unroll
            for (int nf2 = 0; nf2 < 4; nf2++) {
                uint32_t off = SWZ128((uint32_t)((b_r + nf2 * 16) * 128 + (b_g + 2 * ks) * 16));
                ldsm4(&bh[nf2 * 4], sBh + off);
                ldsm4(&bl[nf2 * 4], sBl + off);
            }
#pragma unroll
            for (int nf = 0; nf < 8; nf++)
#pragma unroll
                for (int mt = 0; mt < 2; mt++)
                    mma16816(Creg[mt][nf], ah[mt], &bh[nf * 2]);
#pragma unroll
            for (int nf = 0; nf < 8; nf++)
#pragma unroll
                for (int mt = 0; mt < 2; mt++)
                    mma16816(Creg[mt][nf], ah[mt], &bl[nf * 2]);
#pragma unroll
            for (int nf = 0; nf < 8; nf++)
#pragma unroll
                for (int mt = 0; mt < 2; mt++)
                    mma16816(Creg[mt][nf], al[mt], &bh[nf * 2]);
        }
        __syncthreads();
        if (c + 2 < NCH) { load_chunk(c + 2, buf); CP_COMMIT(); }
    }

#pragma unroll
    for (int mt = 0; mt < 2; mt++) {
#pragma unroll
        for (int nf = 0; nf < 8; nf++) {
            int r0 = m0 + m_base + mt * 16 + (lane >> 2);
            int col = n0 + n_base + nf * 8 + (lane & 3) * 2;
            float2 bv = *(const float2*)&bias[col];
            float* cc = Creg[mt][nf];
            float c00 = cc[0] + bv.x, c01 = cc[1] + bv.y;
            float c10 = cc[2] + bv.x, c11 = cc[3] + bv.y;
            if (Cf == nullptr) {
                uint32_t h0 = pack_bf16(c00, c01);
                uint32_t h1 = pack_bf16(c10, c11);
                __nv_bfloat162 hh0 = *(__nv_bfloat162*)&h0;
                __nv_bfloat162 hh1 = *(__nv_bfloat162*)&h1;
                uint32_t lo0 = pack_bf16(c00 - __bfloat162float(hh0.x), c01 - __bfloat162float(hh0.y));
                uint32_t lo1 = pack_bf16(c10 - __bfloat162float(hh1.x), c11 - __bfloat162float(hh1.y));
                *(uint32_t*)&ga.ovh[(size_t)r0 * DIM + col] = h0;
                *(uint32_t*)&ga.ovl[(size_t)r0 * DIM + col] = lo0;
                *(uint32_t*)&ga.ovh[(size_t)(r0 + 8) * DIM + col] = h1;
                *(uint32_t*)&ga.ovl[(size_t)(r0 + 8) * DIM + col] = lo1;
            } else {
                *(float2*)&Cf[(size_t)r0 * DIM + col] = {c00, c01};
                *(float2*)&Cf[(size_t)(r0 + 8) * DIM + col] = {c10, c11};
            }
        }
    }
}

// ---------------- fused RMSNorm + RoPE -> bf16 hi/lo (q and k) ----------------
__global__ __launch_bounds__(256) void rmsnorm_rope_split2(
    const float* __restrict__ xq, const float* __restrict__ xk,
    const float* __restrict__ gqv, const float* __restrict__ gkv,
    __nv_bfloat16* __restrict__ qh, __nv_bfloat16* __restrict__ ql,
    __nv_bfloat16* __restrict__ kh, __nv_bfloat16* __restrict__ kl) {
    int row = blockIdx.x;
    int which = blockIdx.y;
    const float* xp = (which ? xk : xq) + (size_t)row * DIM;
    const float* g = which ? gkv : gqv;
    __nv_bfloat16* oh = which ? kh : qh;
    __nv_bfloat16* ol = which ? kl : ql;
    float outscale = which ? 1.0f : 0.08838834764831845f;
    int tid = threadIdx.x;

    float ss = 0.f;
    for (int i = tid; i < DIM; i += 256) {
        float v = xp[i];
        ss += v * v;
    }
    __shared__ float red[8];
#pragma unroll
    for (int m = 16; m; m >>= 1) ss += __shfl_xor_sync(0xffffffffu, ss, m);
    if ((tid & 31) == 0) red[tid >> 5] = ss;
    __syncthreads();
    if (tid < 8) {
        float v = red[tid];
#pragma unroll
        for (int m = 4; m; m >>= 1) v += __shfl_xor_sync(0xffu, v, m);
        if (tid == 0) red[0] = rsqrtf(v * (1.0f / DIM) + 1e-6f);
    }
    __syncthreads();
    float scale = red[0];

    for (int p = tid; p < NH * NPAIR; p += 256) {
        int head = p >> 6, j = p & 63;
        int i0 = head * HD + 2 * j;
        float2 v = *(const float2*)&xp[i0];
        float2 gv = *(const float2*)&g[i0];
        float xr = v.x * scale * gv.x;
        float xi = v.y * scale * gv.y;
        float c = g_cos[row * NPAIR + j];
        float s = g_sin[row * NPAIR + j];
        float yr = (xr * c - xi * s) * outscale;
        float yi = (xr * s + xi * c) * outscale;
        __nv_bfloat16 hr = __float2bfloat16(yr);
        __nv_bfloat16 hi = __float2bfloat16(yi);
        __nv_bfloat16 lr = __float2bfloat16(yr - __bfloat162float(hr));
        __nv_bfloat16 li = __float2bfloat16(yi - __bfloat162float(hi));
        *(__nv_bfloat162*)&oh[(size_t)row * DIM + i0] = {hr, hi};
        *(__nv_bfloat162*)&ol[(size_t)row * DIM + i0] = {lr, li};
    }
}

// ---------------- persistent HMMA flash attention (delayed PV) --------------
// Smem: Qh[0,32768) Ql[32768,65536) K-ring 2x32768 @65536, V-ring 3x32768 @131072,
// work-broadcast slot @229376.
#define ATT_Q    0
#define ATT_K    65536
#define ATT_V    131072
#define ATT_WS   229376
#define ATT_SMEM (229376 + 32)

__global__ __launch_bounds__(256, 1) void attention_hmma(
    const __nv_bfloat16* __restrict__ Qh, const __nv_bfloat16* __restrict__ Ql,
    const __nv_bfloat16* __restrict__ Kh, const __nv_bfloat16* __restrict__ Kl,
    const __nv_bfloat16* __restrict__ Vh, const __nv_bfloat16* __restrict__ Vl,
    __nv_bfloat16* __restrict__ Oh, __nv_bfloat16* __restrict__ Ol) {
    extern __shared__ char dsm[];
    uint32_t sbase = smem_u32(dsm);
    int* wslot = (int*)(dsm + ATT_WS);

    int tid = threadIdx.x, wid = tid >> 5, lane = tid & 31;

    int a_r = wid * 16 + (lane & 7) + ((lane >> 3) & 1) * 8;
    int a_half = lane >> 4;
    int b_r = ((lane >> 4) & 1) * 8 + (lane & 7);
    int b_half = (lane >> 3) & 1;
    int v_r = (lane & 15);
    int vg = (lane >> 4);

    for (;;) {
        // ---- acquire work item (all warps synced => prior item fully done) ----
        if (tid == 0) wslot[0] = atomicAdd(&g_work, 1);
        __syncthreads();
        int item = wslot[0];
        if (item >= N_ITEM) return;
        int qb = N_QB - 1 - item / NH;   // heavy-first
        int h = item % NH;
        int q0 = qb * 128;

        // ---- load Q ----
        {
            const __nv_bfloat16* gq[2] = {Qh, Ql};
#pragma unroll
            for (int op = 0; op < 2; op++) {
                const __nv_bfloat16* src = gq[op] + (size_t)q0 * DIM + h * HD;
                uint32_t dst = sbase + ATT_Q + (uint32_t)op * 32768;
#pragma unroll
                for (int it = 0; it < 8; it++) {
                    int idx = it * 256 + tid;
                    int r = idx >> 4, gg = idx & 15;
                    uint32_t off = (uint32_t)((gg >> 3) * 16384) + SWZ128((uint32_t)(r * 128 + (gg & 7) * 16));
                    CP_ASYNC16(dst + off, src + (size_t)r * DIM + gg * 8);
                }
            }
            CP_COMMIT();
        }

        const __nv_bfloat16* gkv[4] = {Kh, Kl, Vh, Vl};
        auto load_kv = [&](int t) {
            int k0 = t * 64;
            uint32_t kb = sbase + ATT_K + (uint32_t)(t & 1) * 32768;
            uint32_t vb = sbase + ATT_V + (uint32_t)(t % 3) * 32768;
            uint32_t dsts[4] = {kb, kb + 16384, vb, vb + 16384};
#pragma unroll
            for (int op = 0; op < 4; op++) {
                const __nv_bfloat16* src = gkv[op] + (size_t)k0 * DIM + h * HD;
#pragma unroll
                for (int it = 0; it < 4; it++) {
                    int idx = it * 256 + tid;
                    int r = idx >> 4, gg = idx & 15;
                    uint32_t off = (uint32_t)((gg >> 3) * 8192) + SWZ128((uint32_t)(r * 128 + (gg & 7) * 16));
                    CP_ASYNC16(dsts[op] + off, src + (size_t)r * DIM + gg * 8);
                }
            }
        };

        float O[16][4];
#pragma unroll
        for (int i = 0; i < 16; i++)
#pragma unroll
            for (int j = 0; j < 4; j++) O[i][j] = 0.f;
        float m0 = -1e30f, m1 = -1e30f, l0 = 0.f, l1 = 0.f;
        uint32_t PhP[4][4], PlP[4][4];

        int r0g = q0 + wid * 16 + (lane >> 2);
        int fr0 = r0g / FRAME, fr1 = (r0g + 8) / FRAME;
        int blkmin_f = q0 / FRAME;
        int fqmax = (q0 + 127) / FRAME;
        int ntile = ((fqmax + 1) * FRAME + 63) >> 6;

        load_kv(0); CP_COMMIT();
        load_kv(1); CP_COMMIT();

        for (int t = 0; t < ntile; t++) {
            if (t == ntile - 1) CP_WAIT0(); else CP_WAIT1();
            __syncthreads();

            int k0 = t * 64;
            uint32_t kb = sbase + ATT_K + (uint32_t)(t & 1) * 32768;
            uint32_t bKh = kb, bKl = kb + 16384;

            // ---- S = Q K^T ----
            float S[8][4];
#pragma unroll
            for (int i = 0; i < 8; i++)
#pragma unroll
                for (int j = 0; j < 4; j++) S[i][j] = 0.f;

#pragma unroll
            for (int ks = 0; ks < 8; ks++) {
                uint32_t qa[4], ql4[4], kh4[16], kl4[16];
                uint32_t gq16 = (uint32_t)(((ks & 3) * 2 + a_half) * 16);
                uint32_t aoff = (uint32_t)((ks >> 2) * 16384) + SWZ128((uint32_t)(a_r * 128) + gq16);
                ldsm4(qa, sbase + ATT_Q + aoff);
                ldsm4(ql4, sbase + ATT_Q + 32768 + aoff);
                uint32_t gk16 = (uint32_t)(((ks & 3) * 2 + b_half) * 16);
#pragma unroll
                for (int nb = 0; nb < 4; nb++) {
                    uint32_t boff = (uint32_t)((ks >> 2) * 8192) +
                                    SWZ128((uint32_t)((nb * 16 + b_r) * 128) + gk16);
                    ldsm4(&kh4[nb * 4], bKh + boff);
                    ldsm4(&kl4[nb * 4], bKl + boff);
                }
#pragma unroll
                for (int nf = 0; nf < 8; nf++) mma16816(S[nf], qa, &kh4[nf * 2]);
#pragma unroll
                for (int nf = 0; nf < 8; nf++) mma16816(S[nf], qa, &kl4[nf * 2]);
#pragma unroll
                for (int nf = 0; nf < 8; nf++) mma16816(S[nf], ql4, &kh4[nf * 2]);
            }

            // ---- delayed PV: O += P(t-1) V(t-1) (overlaps softmax below) ----
            if (t > 0) {
                uint32_t vb = sbase + ATT_V + (uint32_t)((t - 1) % 3) * 32768;
                uint32_t bVh = vb, bVl = vb + 16384;
#pragma unroll
                for (int j = 0; j < 4; j++) {
#pragma unroll
                    for (int dp = 0; dp < 4; dp++) {
                        int db0 = 2 * dp, db1 = 2 * dp + 1;
                        uint32_t row = (uint32_t)((j * 16 + v_r) * 128);
                        uint32_t voff0 = (uint32_t)((db0 >> 2) * 8192) +
                                         SWZ128(row + (uint32_t)(((db0 & 3) * 2 + vg) * 16));
                        uint32_t voff1 = (uint32_t)((db1 >> 2) * 8192) +
                                         SWZ128(row + (uint32_t)(((db1 & 3) * 2 + vg) * 16));
                        uint32_t vh_a[4], vh_b[4], vl_a[4], vl_b[4];
                        ldsm4t(vh_a, bVh + voff0);
                        ldsm4t(vh_b, bVh + voff1);
                        ldsm4t(vl_a, bVl + voff0);
                        ldsm4t(vl_b, bVl + voff1);
                        float* o0 = O[4 * dp + 0];
                        float* o1 = O[4 * dp + 1];
                        float* o2 = O[4 * dp + 2];
                        float* o3 = O[4 * dp + 3];
                        mma16816(o0, PhP[j], &vh_a[0]);
                        mma16816(o1, PhP[j], &vh_a[2]);
                        mma16816(o2, PhP[j], &vh_b[0]);
                        mma16816(o3, PhP[j], &vh_b[2]);
                        mma16816(o0, PhP[j], &vl_a[0]);
                        mma16816(o1, PhP[j], &vl_a[2]);
                        mma16816(o2, PhP[j], &vl_b[0]);
                        mma16816(o3, PhP[j], &vl_b[2]);
                        mma16816(o0, PlP[j], &vh_a[0]);
                        mma16816(o1, PlP[j], &vh_a[2]);
                        mma16816(o2, PlP[j], &vh_b[0]);
                        mma16816(o3, PlP[j], &vh_b[2]);
                    }
                }
            }

            // ---- mask ----
            if ((k0 + 63) / FRAME > blkmin_f) {
#pragma unroll
                for (int nf = 0; nf < 8; nf++) {
                    int c = k0 + nf * 8 + 2 * (lane & 3);
                    int cf0 = c / FRAME, cf1 = (c + 1) / FRAME;
                    if (cf0 > fr0) S[nf][0] = -1e30f;
                    if (cf1 > fr0) S[nf][1] = -1e30f;
                    if (cf0 > fr1) S[nf][2] = -1e30f;
                    if (cf1 > fr1) S[nf][3] = -1e30f;
                }
            }

            // ---- online softmax ----
            float mx0 = -1e30f, mx1 = -1e30f;
#pragma unroll
            for (int nf = 0; nf < 8; nf++) {
                mx0 = fmaxf(mx0, fmaxf(S[nf][0], S[nf][1]));
                mx1 = fmaxf(mx1, fmaxf(S[nf][2], S[nf][3]));
            }
            mx0 = fmaxf(mx0, __shfl_xor_sync(0xffffffffu, mx0, 1));
            mx0 = fmaxf(mx0, __shfl_xor_sync(0xffffffffu, mx0, 2));
            mx1 = fmaxf(mx1, __shfl_xor_sync(0xffffffffu, mx1, 1));
            mx1 = fmaxf(mx1, __shfl_xor_sync(0xffffffffu, mx1, 2));
            float mn0 = fmaxf(m0, mx0), mn1 = fmaxf(m1, mx1);
            float al0 = __expf(m0 - mn0), al1 = __expf(m1 - mn1);
            m0 = mn0; m1 = mn1;
#pragma unroll
            for (int i = 0; i < 16; i++) {
                O[i][0] *= al0; O[i][1] *= al0;
                O[i][2] *= al1; O[i][3] *= al1;
            }

            float ps0 = 0.f, ps1 = 0.f;
#pragma unroll
            for (int j = 0; j < 4; j++) {
                float p00 = __expf(S[2 * j][0] - mn0);
                float p01 = __expf(S[2 * j][1] - mn0);
                float p02 = __expf(S[2 * j][2] - mn1);
                float p03 = __expf(S[2 * j][3] - mn1);
                float p10 = __expf(S[2 * j + 1][0] - mn0);
                float p11 = __expf(S[2 * j + 1][1] - mn0);
                float p12 = __expf(S[2 * j + 1][2] - mn1);
                float p13 = __expf(S[2 * j + 1][3] - mn1);
                ps0 += (p00 + p01) + (p10 + p11);
                ps1 += (p02 + p03) + (p12 + p13);
                PhP[j][0] = pack_bf16(p00, p01);
                PhP[j][1] = pack_bf16(p02, p03);
                PhP[j][2] = pack_bf16(p10, p11);
                PhP[j][3] = pack_bf16(p12, p13);
                __nv_bfloat162 h0 = *(__nv_bfloat162*)&PhP[j][0];
                __nv_bfloat162 h1 = *(__nv_bfloat162*)&PhP[j][1];
                __nv_bfloat162 h2 = *(__nv_bfloat162*)&PhP[j][2];
                __nv_bfloat162 h3 = *(__nv_bfloat162*)&PhP[j][3];
                PlP[j][0] = pack_bf16(p00 - __bfloat162float(h0.x), p01 - __bfloat162float(h0.y));
                PlP[j][1] = pack_bf16(p02 - __bfloat162float(h1.x), p03 - __bfloat162float(h1.y));
                PlP[j][2] = pack_bf16(p10 - __bfloat162float(h2.x), p11 - __bfloat162float(h2.y));
                PlP[j][3] = pack_bf16(p12 - __bfloat162float(h3.x), p13 - __bfloat162float(h3.y));
            }
            ps0 += __shfl_xor_sync(0xffffffffu, ps0, 1);
            ps0 += __shfl_xor_sync(0xffffffffu, ps0, 2);
            ps1 += __shfl_xor_sync(0xffffffffu, ps1, 1);
            ps1 += __shfl_xor_sync(0xffffffffu, ps1, 2);
            l0 = l0 * al0 + ps0;
            l1 = l1 * al1 + ps1;

            __syncthreads();
            if (t + 2 < ntile) { load_kv(t + 2); CP_COMMIT(); }
        }

        // ---- final PV ----
        {
            uint32_t vb = sbase + ATT_V + (uint32_t)((ntile - 1) % 3) * 32768;
            uint32_t bVh = vb, bVl = vb + 16384;
#pragma unroll
            for (int j = 0; j < 4; j++) {
#pragma unroll
                for (int dp = 0; dp < 4; dp++) {
                    int db0 = 2 * dp, db1 = 2 * dp + 1;
                    uint32_t row = (uint32_t)((j * 16 + v_r) * 128);
                    uint32_t voff0 = (uint32_t)((db0 >> 2) * 8192) +
                                     SWZ128(row + (uint32_t)(((db0 & 3) * 2 + vg) * 16));
                    uint32_t voff1 = (uint32_t)((db1 >> 2) * 8192) +
                                     SWZ128(row + (uint32_t)(((db1 & 3) * 2 + vg) * 16));
                    uint32_t vh_a[4], vh_b[4], vl_a[4], vl_b[4];
                    ldsm4t(vh_a, bVh + voff0);
                    ldsm4t(vh_b, bVh + voff1);
                    ldsm4t(vl_a, bVl + voff0);
                    ldsm4t(vl_b, bVl + voff1);
                    float* o0 = O[4 * dp + 0];
                    float* o1 = O[4 * dp + 1];
                    float* o2 = O[4 * dp + 2];
                    float* o3 = O[4 * dp + 3];
                    mma16816(o0, PhP[j], &vh_a[0]);
                    mma16816(o1, PhP[j], &vh_a[2]);
                    mma16816(o2, PhP[j], &vh_b[0]);
                    mma16816(o3, PhP[j], &vh_b[2]);
                    mma16816(o0, PhP[j], &vl_a[0]);
                    mma16816(o1, PhP[j], &vl_a[2]);
                    mma16816(o2, PhP[j], &vl_b[0]);
                    mma16816(o3, PhP[j], &vl_b[2]);
                    mma16816(o0, PlP[j], &vh_a[0]);
                    mma16816(o1, PlP[j], &vh_a[2]);
                    mma16816(o2, PlP[j], &vh_b[0]);
                    mma16816(o3, PlP[j], &vh_b[2]);
                }
            }
        }

        // ---- epilogue ----
        float inv0 = 1.0f / l0, inv1 = 1.0f / l1;
        int row0 = q0 + wid * 16 + (lane >> 2);
#pragma unroll
        for (int nf = 0; nf < 16; nf++) {
            int col = h * HD + nf * 8 + 2 * (lane & 3);
            float o00 = O[nf][0] * inv0, o01 = O[nf][1] * inv0;
            float o10 = O[nf][2] * inv1, o11 = O[nf][3] * inv1;
            uint32_t h0 = pack_bf16(o00, o01);
            uint32_t h1 = pack_bf16(o10, o11);
            __nv_bfloat162 hh0 = *(__nv_bfloat162*)&h0;
            __nv_bfloat162 hh1 = *(__nv_bfloat162*)&h1;
            uint32_t lo0 = pack_bf16(o00 - __bfloat162float(hh0.x), o01 - __bfloat162float(hh0.y));
            uint32_t lo1 = pack_bf16(o10 - __bfloat162float(hh1.x), o11 - __bfloat162float(hh1.y));
            *(uint32_t*)&Oh[(size_t)row0 * DIM + col] = h0;
            *(uint32_t*)&Ol[(size_t)row0 * DIM + col] = lo0;
            *(uint32_t*)&Oh[(size_t)(row0 + 8) * DIM + col] = h1;
            *(uint32_t*)&Ol[(size_t)(row0 + 8) * DIM + col] = lo1;
        }
    }
}

// ---------------- launch ----------------
extern "C" void kernel_launch(void* const* d_in, const int* in_sizes, int n_in,
                              void* d_out, int out_size) {
    const float* x  = (const float*)d_in[0];
    const float* Wq = (const float*)d_in[1];
    const float* bq = (const float*)d_in[2];
    const float* Wk = (const float*)d_in[3];
    const float* bk = (const float*)d_in[4];
    const float* Wv = (const float*)d_in[5];
    const float* bv = (const float*)d_in[6];
    const float* Wo = (const float*)d_in[7];
    const float* bo = (const float*)d_in[8];
    const float* gq = (const float*)d_in[9];
    const float* gk = (const float*)d_in[10];
    const float* ff = (const float*)d_in[11];
    const float* fh = (const float*)d_in[12];
    const float* fw = (const float*)d_in[13];
    float* out = (float*)d_out;

    float *qp, *kp;
    __nv_bfloat16 *ah, *al, *qh, *ql, *kh, *kl, *vh, *vl, *whb, *wlb;
    int* workp;
    cudaGetSymbolAddress((void**)&qp, g_q);
    cudaGetSymbolAddress((void**)&kp, g_k);
    cudaGetSymbolAddress((void**)&ah, g_ah);
    cudaGetSymbolAddress((void**)&al, g_al);
    cudaGetSymbolAddress((void**)&whb, g_wh);
    cudaGetSymbolAddress((void**)&wlb, g_wl);
    cudaGetSymbolAddress((void**)&qh, g_qh);
    cudaGetSymbolAddress((void**)&ql, g_ql);
    cudaGetSymbolAddress((void**)&kh, g_kh);
    cudaGetSymbolAddress((void**)&kl, g_kl);
    cudaGetSymbolAddress((void**)&vh, g_vh);
    cudaGetSymbolAddress((void**)&vl, g_vl);
    cudaGetSymbolAddress((void**)&workp, g_work);

    cudaFuncSetAttribute(gemm_hmma,
                         cudaFuncAttributeMaxDynamicSharedMemorySize, GSMEM);
    cudaFuncSetAttribute(attention_hmma,
                         cudaFuncAttributeMaxDynamicSharedMemorySize, ATT_SMEM);

    cudaMemsetAsync(workp, 0, sizeof(int));

    angles_kernel<<<(L_TOK * NPAIR + 255) / 256, 256>>>(ff, fh, fw);

    const int NELT = L_TOK * DIM;
    split_kernel<<<(NELT / 4 + 255) / 256, 256>>>(x, ah, al, NELT);

    transpose_split4_kernel<<<dim3(DIM / 32, DIM / 32, 4), dim3(32, 8)>>>(
        Wq, Wk, Wv, Wo, whb, wlb);

    const size_t WSZ = (size_t)DIM * DIM;
    GemmArgs ga;
    ga.wh0 = whb;           ga.wl0 = wlb;           ga.b0 = bq; ga.o0 = qp;
    ga.wh1 = whb + WSZ;     ga.wl1 = wlb + WSZ;     ga.b1 = bk; ga.o1 = kp;
    ga.wh2 = whb + 2 * WSZ; ga.wl2 = wlb + 2 * WSZ; ga.b2 = bv;
    ga.ovh = vh;            ga.ovl = vl;
    gemm_hmma<<<dim3(DIM / 128, L_TOK / 128, 3), 256, GSMEM>>>(ah, al, ga);

    rmsnorm_rope_split2<<<dim3(L_TOK, 2), 256>>>(qp, kp, gq, gk, qh, ql, kh, kl);

    attention_hmma<<<148, 256, ATT_SMEM>>>(qh, ql, kh, kl, vh, vl, ah, al);

    GemmArgs go;
    go.wh0 = whb + 3 * WSZ; go.wl0 = wlb + 3 * WSZ; go.b0 = bo; go.o0 = out;
    go.wh1 = go.wh0; go.wl1 = go.wl0; go.b1 = bo; go.o1 = out;
    go.wh2 = go.wh0; go.wl2 = go.wl0; go.b2 = bo;
    go.ovh = vh; go.ovl = vl;
    gemm_hmma<<<dim3(DIM / 128, L_TOK / 128, 1), 256, GSMEM>>>(ah, al, go);
}

// round 11
// speedup vs baseline: 1.5609x; 1.3496x over previous
#include <cuda_runtime.h>
#include <cuda_fp16.h>
#include <math.h>
#include <stdint.h>

#define L_TOK 3840
#define DIM   1536
#define NH    12
#define HD    128
#define FRAME 480
#define NPAIR 64
#define N_QB  30
#define N_ITEM (N_QB * NH)

// ---------------- device scratch (no allocs allowed) ----------------
__device__ float g_q[L_TOK * DIM];
__device__ float g_k[L_TOK * DIM];
__device__ float g_cos[L_TOK * NPAIR];
__device__ float g_sin[L_TOK * NPAIR];
__device__ int   g_work;
__device__ __half g_ah[L_TOK * DIM];      // A hi (x, later attn out)
__device__ __half g_al[L_TOK * DIM];      // A lo
__device__ __half g_wh[4][DIM * DIM];     // W^T fp16 (single) for q,k,v,o
__device__ __half g_qh[L_TOK * DIM];
__device__ __half g_ql[L_TOK * DIM];
__device__ __half g_kh[L_TOK * DIM];      // K single fp16
__device__ __half g_vh[L_TOK * DIM];      // V single fp16

// =================== sm_80-era PTX helpers (valid on plain sm_103) ==========
__device__ __forceinline__ uint32_t smem_u32(const void* p) {
    uint32_t a;
    asm("{ .reg .u64 t; cvta.to.shared.u64 t, %1; cvt.u32.u64 %0, t; }" : "=r"(a) : "l"(p));
    return a;
}
#define CP_ASYNC16(dst, src) \
    asm volatile("cp.async.cg.shared.global [%0], [%1], 16;" :: "r"(dst), "l"(src))
#define CP_COMMIT() asm volatile("cp.async.commit_group;" ::: "memory")
#define CP_WAIT1()  asm volatile("cp.async.wait_group 1;" ::: "memory")
#define CP_WAIT0()  asm volatile("cp.async.wait_group 0;" ::: "memory")

__device__ __forceinline__ void ldsm4(uint32_t* r, uint32_t addr) {
    asm volatile("ldmatrix.sync.aligned.m8n8.x4.shared.b16 {%0,%1,%2,%3}, [%4];"
                 : "=r"(r[0]), "=r"(r[1]), "=r"(r[2]), "=r"(r[3]) : "r"(addr));
}
__device__ __forceinline__ void ldsm4t(uint32_t* r, uint32_t addr) {
    asm volatile("ldmatrix.sync.aligned.m8n8.x4.trans.shared.b16 {%0,%1,%2,%3}, [%4];"
                 : "=r"(r[0]), "=r"(r[1]), "=r"(r[2]), "=r"(r[3]) : "r"(addr));
}
__device__ __forceinline__ void mma16816(float* c, const uint32_t* a, const uint32_t* b) {
    asm volatile("mma.sync.aligned.m16n8k16.row.col.f32.f16.f16.f32 "
                 "{%0,%1,%2,%3}, {%4,%5,%6,%7}, {%8,%9}, {%0,%1,%2,%3};"
                 : "+f"(c[0]), "+f"(c[1]), "+f"(c[2]), "+f"(c[3])
                 : "r"(a[0]), "r"(a[1]), "r"(a[2]), "r"(a[3]), "r"(b[0]), "r"(b[1]));
}
#define SWZ128(off) ((off) ^ (((off) >> 3) & 0x70))

__device__ __forceinline__ uint32_t pack_f16(float lo, float hi) {
    uint32_t r;
    asm("cvt.rn.f16x2.f32 %0, %1, %2;" : "=r"(r) : "f"(hi), "f"(lo));
    return r;
}

// ---------------- angle table ----------------
__global__ void angles_kernel(const float* __restrict__ ff,
                              const float* __restrict__ fh,
                              const float* __restrict__ fw) {
    int idx = blockIdx.x * blockDim.x + threadIdx.x;
    if (idx >= L_TOK * NPAIR) return;
    int l = idx / NPAIR, j = idx % NPAIR;
    int f = l / FRAME, r = l % FRAME;
    int h = r / 30, w = r % 30;
    float a;
    if (j < 22)      a = ff[f * 22 + j];
    else if (j < 43) a = fh[h * 21 + (j - 22)];
    else             a = fw[w * 21 + (j - 43)];
    g_cos[idx] = cosf(a);
    g_sin[idx] = sinf(a);
}

// ---------------- split fp32 -> fp16 hi/lo ----------------
__global__ __launch_bounds__(256) void split_kernel(const float* __restrict__ x,
                                                    __half* __restrict__ hi,
                                                    __half* __restrict__ lo, int n) {
    int i = blockIdx.x * blockDim.x + threadIdx.x;
    if (i * 4 >= n) return;
    float4 v = *(const float4*)&x[i * 4];
    __half h0 = __float2half(v.x), h1 = __float2half(v.y);
    __half h2 = __float2half(v.z), h3 = __float2half(v.w);
    __half l0 = __float2half(v.x - __half2float(h0));
    __half l1 = __float2half(v.y - __half2float(h1));
    __half l2 = __float2half(v.z - __half2float(h2));
    __half l3 = __float2half(v.w - __half2float(h3));
    __half2* ph = (__half2*)&hi[i * 4];
    __half2* pl = (__half2*)&lo[i * 4];
    ph[0] = {h0, h1}; ph[1] = {h2, h3};
    pl[0] = {l0, l1}; pl[1] = {l2, l3};
}

// ------- fused transpose of 4 weights [K,N] -> [N,K], single fp16 -------
__global__ __launch_bounds__(256) void transpose_half4_kernel(
    const float* __restrict__ W0, const float* __restrict__ W1,
    const float* __restrict__ W2, const float* __restrict__ W3,
    __half* __restrict__ ThBase) {
    __shared__ float t[32][33];
    int z = blockIdx.z;
    const float* W = (z == 0) ? W0 : (z == 1) ? W1 : (z == 2) ? W2 : W3;
    __half* Th = ThBase + (size_t)z * DIM * DIM;
    int tx = threadIdx.x, ty = threadIdx.y;  // 32 x 8
    int x0 = blockIdx.x * 32, y0 = blockIdx.y * 32;
#pragma unroll
    for (int i = 0; i < 32; i += 8)
        t[ty + i][tx] = W[(size_t)(y0 + ty + i) * DIM + x0 + tx];
    __syncthreads();
#pragma unroll
    for (int i = 0; i < 32; i += 8)
        Th[(size_t)(x0 + ty + i) * DIM + y0 + tx] = __float2half(t[tx][ty + i]);
}

// ---------------- HMMA fp16 2-term GEMM (256t, 2-stage) ----------------
// C = A @ W + bias ; A = Ah+Al fp16 [M,K], B = W^T fp16 single [N,K].
// C ≈ Ah·Bh + Al·Bh.
#define GK       64
#define TILE_B   16384
#define BUF_B    (3 * TILE_B)     // Ah, Al, Bh
#define GSMEM    (1024 + 2 * BUF_B)

struct GemmArgs {
    const __half *wh0, *wh1, *wh2;
    const float *b0, *b1, *b2;
    float *o0, *o1;
    __half *ovh;                  // single fp16 output for z=2 (V)
};

__global__ __launch_bounds__(256, 1) void gemm_hmma(const __half* __restrict__ Ah,
                                                    const __half* __restrict__ Al,
                                                    GemmArgs ga) {
    extern __shared__ char dsm[];
    uint32_t raw = smem_u32(dsm);
    uint32_t sbase = (raw + 1023u) & ~1023u;

    int tid = threadIdx.x;
    int wid = tid >> 5, lane = tid & 31;
    int m0 = blockIdx.y * 128;
    int n0 = blockIdx.x * 128;

    const __half* Bh;
    const float* bias;
    float* Cf;
    if (blockIdx.z == 0)      { Bh = ga.wh0; bias = ga.b0; Cf = ga.o0; }
    else if (blockIdx.z == 1) { Bh = ga.wh1; bias = ga.b1; Cf = ga.o1; }
    else                      { Bh = ga.wh2; bias = ga.b2; Cf = nullptr; }

    const __half* srcs[3] = {Ah, Al, Bh};
    const int rbase[3] = {m0, m0, n0};

    auto load_chunk = [&](int c, int buf) {
        uint32_t dst0 = sbase + (uint32_t)buf * BUF_B;
#pragma unroll
        for (int it = 0; it < 12; it++) {
            int idx = it * 256 + tid;
            int tile = idx >> 10;
            int rem = idx & 1023;
            int r = rem >> 3, g = rem & 7;
            const __half* src = srcs[tile] + (size_t)(rbase[tile] + r) * DIM + c * GK + g * 8;
            uint32_t off = (uint32_t)(r * 128 + g * 16);
            CP_ASYNC16(dst0 + (uint32_t)tile * TILE_B + SWZ128(off), src);
        }
    };

    float Creg[2][8][4];
#pragma unroll
    for (int mt = 0; mt < 2; mt++)
#pragma unroll
        for (int nf = 0; nf < 8; nf++)
#pragma unroll
            for (int j = 0; j < 4; j++) Creg[mt][nf][j] = 0.f;

    int m_base = (wid & 3) * 32;
    int n_base = (wid >> 2) * 64;
    int a_r = m_base + (lane & 7) + ((lane >> 3) & 1) * 8;
    int a_g = (lane >> 4);
    int b_r = n_base + ((lane >> 4) & 1) * 8 + (lane & 7);
    int b_g = (lane >> 3) & 1;

    const int NCH = DIM / GK;
    load_chunk(0, 0); CP_COMMIT();
    load_chunk(1, 1); CP_COMMIT();

    for (int c = 0; c < NCH; c++) {
        if (c == NCH - 1) CP_WAIT0(); else CP_WAIT1();
        __syncthreads();

        int buf = c & 1;
        uint32_t sb = sbase + (uint32_t)buf * BUF_B;
        uint32_t sAh = sb, sAl = sb + TILE_B, sBh = sb + 2 * TILE_B;

#pragma unroll
        for (int ks = 0; ks < 4; ks++) {
            uint32_t ah[2][4], al[2][4], bh[16];
#pragma unroll
            for (int mt = 0; mt < 2; mt++) {
                uint32_t off = SWZ128((uint32_t)((a_r + mt * 16) * 128 + (a_g + 2 * ks) * 16));
                ldsm4(ah[mt], sAh + off);
                ldsm4(al[mt], sAl + off);
            }
#pragma unroll
            for (int nf2 = 0; nf2 < 4; nf2++) {
                uint32_t off = SWZ128((uint32_t)((b_r + nf2 * 16) * 128 + (b_g + 2 * ks) * 16));
                ldsm4(&bh[nf2 * 4], sBh + off);
            }
#pragma unroll
            for (int nf = 0; nf < 8; nf++)
#pragma unroll
                for (int mt = 0; mt < 2; mt++)
                    mma16816(Creg[mt][nf], ah[mt], &bh[nf * 2]);
#pragma unroll
            for (int nf = 0; nf < 8; nf++)
#pragma unroll
                for (int mt = 0; mt < 2; mt++)
                    mma16816(Creg[mt][nf], al[mt], &bh[nf * 2]);
        }
        __syncthreads();
        if (c + 2 < NCH) { load_chunk(c + 2, buf); CP_COMMIT(); }
    }

#pragma unroll
    for (int mt = 0; mt < 2; mt++) {
#pragma unroll
        for (int nf = 0; nf < 8; nf++) {
            int r0 = m0 + m_base + mt * 16 + (lane >> 2);
            int col = n0 + n_base + nf * 8 + (lane & 3) * 2;
            float2 bv = *(const float2*)&bias[col];
            float* cc = Creg[mt][nf];
            float c00 = cc[0] + bv.x, c01 = cc[1] + bv.y;
            float c10 = cc[2] + bv.x, c11 = cc[3] + bv.y;
            if (Cf == nullptr) {
                *(uint32_t*)&ga.ovh[(size_t)r0 * DIM + col] = pack_f16(c00, c01);
                *(uint32_t*)&ga.ovh[(size_t)(r0 + 8) * DIM + col] = pack_f16(c10, c11);
            } else {
                *(float2*)&Cf[(size_t)r0 * DIM + col] = {c00, c01};
                *(float2*)&Cf[(size_t)(r0 + 8) * DIM + col] = {c10, c11};
            }
        }
    }
}

// ---------------- fused RMSNorm + RoPE: q -> fp16 hi/lo, k -> fp16 single ---
__global__ __launch_bounds__(256) void rmsnorm_rope_split2(
    const float* __restrict__ xq, const float* __restrict__ xk,
    const float* __restrict__ gqv, const float* __restrict__ gkv,
    __half* __restrict__ qh, __half* __restrict__ ql,
    __half* __restrict__ kh) {
    int row = blockIdx.x;
    int which = blockIdx.y;
    const float* xp = (which ? xk : xq) + (size_t)row * DIM;
    const float* g = which ? gkv : gqv;
    float outscale = which ? 1.0f : 0.08838834764831845f;
    int tid = threadIdx.x;

    float ss = 0.f;
    for (int i = tid; i < DIM; i += 256) {
        float v = xp[i];
        ss += v * v;
    }
    __shared__ float red[8];
#pragma unroll
    for (int m = 16; m; m >>= 1) ss += __shfl_xor_sync(0xffffffffu, ss, m);
    if ((tid & 31) == 0) red[tid >> 5] = ss;
    __syncthreads();
    if (tid < 8) {
        float v = red[tid];
#pragma unroll
        for (int m = 4; m; m >>= 1) v += __shfl_xor_sync(0xffu, v, m);
        if (tid == 0) red[0] = rsqrtf(v * (1.0f / DIM) + 1e-6f);
    }
    __syncthreads();
    float scale = red[0];

    for (int p = tid; p < NH * NPAIR; p += 256) {
        int head = p >> 6, j = p & 63;
        int i0 = head * HD + 2 * j;
        float2 v = *(const float2*)&xp[i0];
        float2 gv = *(const float2*)&g[i0];
        float xr = v.x * scale * gv.x;
        float xi = v.y * scale * gv.y;
        float c = g_cos[row * NPAIR + j];
        float s = g_sin[row * NPAIR + j];
        float yr = (xr * c - xi * s) * outscale;
        float yi = (xr * s + xi * c) * outscale;
        if (which == 0) {
            __half hr = __float2half(yr);
            __half hi2 = __float2half(yi);
            __half lr = __float2half(yr - __half2float(hr));
            __half li = __float2half(yi - __half2float(hi2));
            *(__half2*)&qh[(size_t)row * DIM + i0] = {hr, hi2};
            *(__half2*)&ql[(size_t)row * DIM + i0] = {lr, li};
        } else {
            *(__half2*)&kh[(size_t)row * DIM + i0] = {__float2half(yr), __float2half(yi)};
        }
    }
}

// ---------------- persistent fp16 flash attention (delayed PV) --------------
// Smem: Qh[0,32768) Ql[32768,65536); K-ring 2x16384 @65536; V-ring 3x16384 @98304;
// work slot @147456.
#define ATT_Q    0
#define ATT_K    65536
#define ATT_V    98304
#define ATT_WS   147456
#define ATT_SMEM (147456 + 32)

__global__ __launch_bounds__(256, 1) void attention_hmma(
    const __half* __restrict__ Qh, const __half* __restrict__ Ql,
    const __half* __restrict__ Kh, const __half* __restrict__ Vh,
    __half* __restrict__ Oh, __half* __restrict__ Ol) {
    extern __shared__ char dsm[];
    uint32_t sbase = smem_u32(dsm);
    int* wslot = (int*)(dsm + ATT_WS);

    int tid = threadIdx.x, wid = tid >> 5, lane = tid & 31;

    int a_r = wid * 16 + (lane & 7) + ((lane >> 3) & 1) * 8;
    int a_half = lane >> 4;
    int b_r = ((lane >> 4) & 1) * 8 + (lane & 7);
    int b_half = (lane >> 3) & 1;
    int v_r = (lane & 15);
    int vg = (lane >> 4);

    for (;;) {
        if (tid == 0) wslot[0] = atomicAdd(&g_work, 1);
        __syncthreads();
        int item = wslot[0];
        if (item >= N_ITEM) return;
        int qb = N_QB - 1 - item / NH;
        int h = item % NH;
        int q0 = qb * 128;

        // ---- load Q (hi+lo) ----
        {
            const __half* gq[2] = {Qh, Ql};
#pragma unroll
            for (int op = 0; op < 2; op++) {
                const __half* src = gq[op] + (size_t)q0 * DIM + h * HD;
                uint32_t dst = sbase + ATT_Q + (uint32_t)op * 32768;
#pragma unroll
                for (int it = 0; it < 8; it++) {
                    int idx = it * 256 + tid;
                    int r = idx >> 4, gg = idx & 15;
                    uint32_t off = (uint32_t)((gg >> 3) * 16384) + SWZ128((uint32_t)(r * 128 + (gg & 7) * 16));
                    CP_ASYNC16(dst + off, src + (size_t)r * DIM + gg * 8);
                }
            }
            CP_COMMIT();
        }

        auto load_kv = [&](int t) {
            int k0 = t * 64;
            uint32_t kdst = sbase + ATT_K + (uint32_t)(t & 1) * 16384;
            uint32_t vdst = sbase + ATT_V + (uint32_t)(t % 3) * 16384;
            const __half* ksrc = Kh + (size_t)k0 * DIM + h * HD;
            const __half* vsrc = Vh + (size_t)k0 * DIM + h * HD;
#pragma unroll
            for (int it = 0; it < 4; it++) {
                int idx = it * 256 + tid;
                int r = idx >> 4, gg = idx & 15;
                uint32_t off = (uint32_t)((gg >> 3) * 8192) + SWZ128((uint32_t)(r * 128 + (gg & 7) * 16));
                CP_ASYNC16(kdst + off, ksrc + (size_t)r * DIM + gg * 8);
                CP_ASYNC16(vdst + off, vsrc + (size_t)r * DIM + gg * 8);
            }
        };

        float O[16][4];
#pragma unroll
        for (int i = 0; i < 16; i++)
#pragma unroll
            for (int j = 0; j < 4; j++) O[i][j] = 0.f;
        float m0 = -1e30f, m1 = -1e30f, l0 = 0.f, l1 = 0.f;
        uint32_t PhP[4][4], PlP[4][4];

        int r0g = q0 + wid * 16 + (lane >> 2);
        int fr0 = r0g / FRAME, fr1 = (r0g + 8) / FRAME;
        int blkmin_f = q0 / FRAME;
        int fqmax = (q0 + 127) / FRAME;
        int ntile = ((fqmax + 1) * FRAME + 63) >> 6;

        load_kv(0); CP_COMMIT();
        load_kv(1); CP_COMMIT();

        for (int t = 0; t < ntile; t++) {
            if (t == ntile - 1) CP_WAIT0(); else CP_WAIT1();
            __syncthreads();

            int k0 = t * 64;
            uint32_t bKh = sbase + ATT_K + (uint32_t)(t & 1) * 16384;

            // ---- S = Q K^T (2-term: Qh*K + Ql*K) ----
            float S[8][4];
#pragma unroll
            for (int i = 0; i < 8; i++)
#pragma unroll
                for (int j = 0; j < 4; j++) S[i][j] = 0.f;

#pragma unroll
            for (int ks = 0; ks < 8; ks++) {
                uint32_t qa[4], ql4[4], kh4[16];
                uint32_t gq16 = (uint32_t)(((ks & 3) * 2 + a_half) * 16);
                uint32_t aoff = (uint32_t)((ks >> 2) * 16384) + SWZ128((uint32_t)(a_r * 128) + gq16);
                ldsm4(qa, sbase + ATT_Q + aoff);
                ldsm4(ql4, sbase + ATT_Q + 32768 + aoff);
                uint32_t gk16 = (uint32_t)(((ks & 3) * 2 + b_half) * 16);
#pragma unroll
                for (int nb = 0; nb < 4; nb++) {
                    uint32_t boff = (uint32_t)((ks >> 2) * 8192) +
                                    SWZ128((uint32_t)((nb * 16 + b_r) * 128) + gk16);
                    ldsm4(&kh4[nb * 4], bKh + boff);
                }
#pragma unroll
                for (int nf = 0; nf < 8; nf++) mma16816(S[nf], qa, &kh4[nf * 2]);
#pragma unroll
                for (int nf = 0; nf < 8; nf++) mma16816(S[nf], ql4, &kh4[nf * 2]);
            }

            // ---- delayed PV: O += P(t-1) V(t-1) (2-term: Ph*V + Pl*V) ----
            if (t > 0) {
                uint32_t bVh = sbase + ATT_V + (uint32_t)((t - 1) % 3) * 16384;
#pragma unroll
                for (int j = 0; j < 4; j++) {
#pragma unroll
                    for (int dp = 0; dp < 4; dp++) {
                        int db0 = 2 * dp, db1 = 2 * dp + 1;
                        uint32_t row = (uint32_t)((j * 16 + v_r) * 128);
                        uint32_t voff0 = (uint32_t)((db0 >> 2) * 8192) +
                                         SWZ128(row + (uint32_t)(((db0 & 3) * 2 + vg) * 16));
                        uint32_t voff1 = (uint32_t)((db1 >> 2) * 8192) +
                                         SWZ128(row + (uint32_t)(((db1 & 3) * 2 + vg) * 16));
                        uint32_t vh_a[4], vh_b[4];
                        ldsm4t(vh_a, bVh + voff0);
                        ldsm4t(vh_b, bVh + voff1);
                        float* o0 = O[4 * dp + 0];
                        float* o1 = O[4 * dp + 1];
                        float* o2 = O[4 * dp + 2];
                        float* o3 = O[4 * dp + 3];
                        mma16816(o0, PhP[j], &vh_a[0]);
                        mma16816(o1, PhP[j], &vh_a[2]);
                        mma16816(o2, PhP[j], &vh_b[0]);
                        mma16816(o3, PhP[j], &vh_b[2]);
                        mma16816(o0, PlP[j], &vh_a[0]);
                        mma16816(o1, PlP[j], &vh_a[2]);
                        mma16816(o2, PlP[j], &vh_b[0]);
                        mma16816(o3, PlP[j], &vh_b[2]);
                    }
                }
            }

            // ---- mask ----
            if ((k0 + 63) / FRAME > blkmin_f) {
#pragma unroll
                for (int nf = 0; nf < 8; nf++) {
                    int c = k0 + nf * 8 + 2 * (lane & 3);
                    int cf0 = c / FRAME, cf1 = (c + 1) / FRAME;
                    if (cf0 > fr0) S[nf][0] = -1e30f;
                    if (cf1 > fr0) S[nf][1] = -1e30f;
                    if (cf0 > fr1) S[nf][2] = -1e30f;
                    if (cf1 > fr1) S[nf][3] = -1e30f;
                }
            }

            // ---- online softmax ----
            float mx0 = -1e30f, mx1 = -1e30f;
#pragma unroll
            for (int nf = 0; nf < 8; nf++) {
                mx0 = fmaxf(mx0, fmaxf(S[nf][0], S[nf][1]));
                mx1 = fmaxf(mx1, fmaxf(S[nf][2], S[nf][3]));
            }
            mx0 = fmaxf(mx0, __shfl_xor_sync(0xffffffffu, mx0, 1));
            mx0 = fmaxf(mx0, __shfl_xor_sync(0xffffffffu, mx0, 2));
            mx1 = fmaxf(mx1, __shfl_xor_sync(0xffffffffu, mx1, 1));
            mx1 = fmaxf(mx1, __shfl_xor_sync(0xffffffffu, mx1, 2));
            float mn0 = fmaxf(m0, mx0), mn1 = fmaxf(m1, mx1);
            float al0 = __expf(m0 - mn0), al1 = __expf(m1 - mn1);
            m0 = mn0; m1 = mn1;
#pragma unroll
            for (int i = 0; i < 16; i++) {
                O[i][0] *= al0; O[i][1] *= al0;
                O[i][2] *= al1; O[i][3] *= al1;
            }

            float ps0 = 0.f, ps1 = 0.f;
#pragma unroll
            for (int j = 0; j < 4; j++) {
                float p00 = __expf(S[2 * j][0] - mn0);
                float p01 = __expf(S[2 * j][1] - mn0);
                float p02 = __expf(S[2 * j][2] - mn1);
                float p03 = __expf(S[2 * j][3] - mn1);
                float p10 = __expf(S[2 * j + 1][0] - mn0);
                float p11 = __expf(S[2 * j + 1][1] - mn0);
                float p12 = __expf(S[2 * j + 1][2] - mn1);
                float p13 = __expf(S[2 * j + 1][3] - mn1);
                ps0 += (p00 + p01) + (p10 + p11);
                ps1 += (p02 + p03) + (p12 + p13);
                PhP[j][0] = pack_f16(p00, p01);
                PhP[j][1] = pack_f16(p02, p03);
                PhP[j][2] = pack_f16(p10, p11);
                PhP[j][3] = pack_f16(p12, p13);
                __half2 h0 = *(__half2*)&PhP[j][0];
                __half2 h1 = *(__half2*)&PhP[j][1];
                __half2 h2 = *(__half2*)&PhP[j][2];
                __half2 h3 = *(__half2*)&PhP[j][3];
                PlP[j][0] = pack_f16(p00 - __half2float(h0.x), p01 - __half2float(h0.y));
                PlP[j][1] = pack_f16(p02 - __half2float(h1.x), p03 - __half2float(h1.y));
                PlP[j][2] = pack_f16(p10 - __half2float(h2.x), p11 - __half2float(h2.y));
                PlP[j][3] = pack_f16(p12 - __half2float(h3.x), p13 - __half2float(h3.y));
            }
            ps0 += __shfl_xor_sync(0xffffffffu, ps0, 1);
            ps0 += __shfl_xor_sync(0xffffffffu, ps0, 2);
            ps1 += __shfl_xor_sync(0xffffffffu, ps1, 1);
            ps1 += __shfl_xor_sync(0xffffffffu, ps1, 2);
            l0 = l0 * al0 + ps0;
            l1 = l1 * al1 + ps1;

            __syncthreads();
            if (t + 2 < ntile) { load_kv(t + 2); CP_COMMIT(); }
        }

        // ---- final PV ----
        {
            uint32_t bVh = sbase + ATT_V + (uint32_t)((ntile - 1) % 3) * 16384;
#pragma unroll
            for (int j = 0; j < 4; j++) {
#pragma unroll
                for (int dp = 0; dp < 4; dp++) {
                    int db0 = 2 * dp, db1 = 2 * dp + 1;
                    uint32_t row = (uint32_t)((j * 16 + v_r) * 128);
                    uint32_t voff0 = (uint32_t)((db0 >> 2) * 8192) +
                                     SWZ128(row + (uint32_t)(((db0 & 3) * 2 + vg) * 16));
                    uint32_t voff1 = (uint32_t)((db1 >> 2) * 8192) +
                                     SWZ128(row + (uint32_t)(((db1 & 3) * 2 + vg) * 16));
                    uint32_t vh_a[4], vh_b[4];
                    ldsm4t(vh_a, bVh + voff0);
                    ldsm4t(vh_b, bVh + voff1);
                    float* o0 = O[4 * dp + 0];
                    float* o1 = O[4 * dp + 1];
                    float* o2 = O[4 * dp + 2];
                    float* o3 = O[4 * dp + 3];
                    mma16816(o0, PhP[j], &vh_a[0]);
                    mma16816(o1, PhP[j], &vh_a[2]);
                    mma16816(o2, PhP[j], &vh_b[0]);
                    mma16816(o3, PhP[j], &vh_b[2]);
                    mma16816(o0, PlP[j], &vh_a[0]);
                    mma16816(o1, PlP[j], &vh_a[2]);
                    mma16816(o2, PlP[j], &vh_b[0]);
                    mma16816(o3, PlP[j], &vh_b[2]);
                }
            }
        }

        // ---- epilogue: normalize, split to fp16 hi/lo, store ----
        float inv0 = 1.0f / l0, inv1 = 1.0f / l1;
        int row0 = q0 + wid * 16 + (lane >> 2);
#pragma unroll
        for (int nf = 0; nf < 16; nf++) {
            int col = h * HD + nf * 8 + 2 * (lane & 3);
            float o00 = O[nf][0] * inv0, o01 = O[nf][1] * inv0;
            float o10 = O[nf][2] * inv1, o11 = O[nf][3] * inv1;
            uint32_t h0 = pack_f16(o00, o01);
            uint32_t h1 = pack_f16(o10, o11);
            __half2 hh0 = *(__half2*)&h0;
            __half2 hh1 = *(__half2*)&h1;
            uint32_t lo0 = pack_f16(o00 - __half2float(hh0.x), o01 - __half2float(hh0.y));
            uint32_t lo1 = pack_f16(o10 - __half2float(hh1.x), o11 - __half2float(hh1.y));
            *(uint32_t*)&Oh[(size_t)row0 * DIM + col] = h0;
            *(uint32_t*)&Ol[(size_t)row0 * DIM + col] = lo0;
            *(uint32_t*)&Oh[(size_t)(row0 + 8) * DIM + col] = h1;
            *(uint32_t*)&Ol[(size_t)(row0 + 8) * DIM + col] = lo1;
        }
    }
}

// ---------------- launch ----------------
extern "C" void kernel_launch(void* const* d_in, const int* in_sizes, int n_in,
                              void* d_out, int out_size) {
    const float* x  = (const float*)d_in[0];
    const float* Wq = (const float*)d_in[1];
    const float* bq = (const float*)d_in[2];
    const float* Wk = (const float*)d_in[3];
    const float* bk = (const float*)d_in[4];
    const float* Wv = (const float*)d_in[5];
    const float* bv = (const float*)d_in[6];
    const float* Wo = (const float*)d_in[7];
    const float* bo = (const float*)d_in[8];
    const float* gq = (const float*)d_in[9];
    const float* gk = (const float*)d_in[10];
    const float* ff = (const float*)d_in[11];
    const float* fh = (const float*)d_in[12];
    const float* fw = (const float*)d_in[13];
    float* out = (float*)d_out;

    float *qp, *kp;
    __half *ah, *al, *qh, *ql, *kh, *vh, *whb;
    int* workp;
    cudaGetSymbolAddress((void**)&qp, g_q);
    cudaGetSymbolAddress((void**)&kp, g_k);
    cudaGetSymbolAddress((void**)&ah, g_ah);
    cudaGetSymbolAddress((void**)&al, g_al);
    cudaGetSymbolAddress((void**)&whb, g_wh);
    cudaGetSymbolAddress((void**)&qh, g_qh);
    cudaGetSymbolAddress((void**)&ql, g_ql);
    cudaGetSymbolAddress((void**)&kh, g_kh);
    cudaGetSymbolAddress((void**)&vh, g_vh);
    cudaGetSymbolAddress((void**)&workp, g_work);

    cudaFuncSetAttribute(gemm_hmma,
                         cudaFuncAttributeMaxDynamicSharedMemorySize, GSMEM);
    cudaFuncSetAttribute(attention_hmma,
                         cudaFuncAttributeMaxDynamicSharedMemorySize, ATT_SMEM);

    cudaMemsetAsync(workp, 0, sizeof(int));

    angles_kernel<<<(L_TOK * NPAIR + 255) / 256, 256>>>(ff, fh, fw);

    const int NELT = L_TOK * DIM;
    split_kernel<<<(NELT / 4 + 255) / 256, 256>>>(x, ah, al, NELT);

    transpose_half4_kernel<<<dim3(DIM / 32, DIM / 32, 4), dim3(32, 8)>>>(
        Wq, Wk, Wv, Wo, whb);

    const size_t WSZ = (size_t)DIM * DIM;
    GemmArgs ga;
    ga.wh0 = whb;           ga.b0 = bq; ga.o0 = qp;
    ga.wh1 = whb + WSZ;     ga.b1 = bk; ga.o1 = kp;
    ga.wh2 = whb + 2 * WSZ; ga.b2 = bv;
    ga.ovh = vh;
    gemm_hmma<<<dim3(DIM / 128, L_TOK / 128, 3), 256, GSMEM>>>(ah, al, ga);

    rmsnorm_rope_split2<<<dim3(L_TOK, 2), 256>>>(qp, kp, gq, gk, qh, ql, kh);

    attention_hmma<<<148, 256, ATT_SMEM>>>(qh, ql, kh, vh, ah, al);

    GemmArgs go;
    go.wh0 = whb + 3 * WSZ; go.b0 = bo; go.o0 = out;
    go.wh1 = go.wh0; go.b1 = bo; go.o1 = out;
    go.wh2 = go.wh0; go.b2 = bo;
    go.ovh = vh;
    gemm_hmma<<<dim3(DIM / 128, L_TOK / 128, 1), 256, GSMEM>>>(ah, al, go);
}

// round 12
// speedup vs baseline: 1.5790x; 1.0116x over previous
#include <cuda_runtime.h>
#include <cuda_fp16.h>
#include <math.h>
#include <stdint.h>

#define L_TOK 3840
#define DIM   1536
#define NH    12
#define HD    128
#define FRAME 480
#define NPAIR 64
#define N_QB  30
#define N_ITEM (N_QB * NH)

// ---------------- device scratch (no allocs allowed) ----------------
__device__ float g_q[L_TOK * DIM];
__device__ float g_k[L_TOK * DIM];
__device__ float g_cos[L_TOK * NPAIR];
__device__ float g_sin[L_TOK * NPAIR];
__device__ int   g_work;
__device__ __half g_ah[L_TOK * DIM];      // A hi (x, later attn out)
__device__ __half g_al[L_TOK * DIM];      // A lo
__device__ __half g_wh[4][DIM * DIM];     // W^T fp16 (single) for q,k,v,o
__device__ __half g_qh[L_TOK * DIM];
__device__ __half g_ql[L_TOK * DIM];
__device__ __half g_kh[L_TOK * DIM];      // K single fp16
__device__ __half g_vh[L_TOK * DIM];      // V single fp16

// =================== sm_80-era PTX helpers (valid on plain sm_103) ==========
__device__ __forceinline__ uint32_t smem_u32(const void* p) {
    uint32_t a;
    asm("{ .reg .u64 t; cvta.to.shared.u64 t, %1; cvt.u32.u64 %0, t; }" : "=r"(a) : "l"(p));
    return a;
}
#define CP_ASYNC16(dst, src) \
    asm volatile("cp.async.cg.shared.global [%0], [%1], 16;" :: "r"(dst), "l"(src))
#define CP_COMMIT() asm volatile("cp.async.commit_group;" ::: "memory")
#define CP_WAIT1()  asm volatile("cp.async.wait_group 1;" ::: "memory")
#define CP_WAIT0()  asm volatile("cp.async.wait_group 0;" ::: "memory")

__device__ __forceinline__ void ldsm4(uint32_t* r, uint32_t addr) {
    asm volatile("ldmatrix.sync.aligned.m8n8.x4.shared.b16 {%0,%1,%2,%3}, [%4];"
                 : "=r"(r[0]), "=r"(r[1]), "=r"(r[2]), "=r"(r[3]) : "r"(addr));
}
__device__ __forceinline__ void ldsm4t(uint32_t* r, uint32_t addr) {
    asm volatile("ldmatrix.sync.aligned.m8n8.x4.trans.shared.b16 {%0,%1,%2,%3}, [%4];"
                 : "=r"(r[0]), "=r"(r[1]), "=r"(r[2]), "=r"(r[3]) : "r"(addr));
}
__device__ __forceinline__ void mma16816(float* c, const uint32_t* a, const uint32_t* b) {
    asm volatile("mma.sync.aligned.m16n8k16.row.col.f32.f16.f16.f32 "
                 "{%0,%1,%2,%3}, {%4,%5,%6,%7}, {%8,%9}, {%0,%1,%2,%3};"
                 : "+f"(c[0]), "+f"(c[1]), "+f"(c[2]), "+f"(c[3])
                 : "r"(a[0]), "r"(a[1]), "r"(a[2]), "r"(a[3]), "r"(b[0]), "r"(b[1]));
}
#define SWZ128(off) ((off) ^ (((off) >> 3) & 0x70))

__device__ __forceinline__ uint32_t pack_f16(float lo, float hi) {
    uint32_t r;
    asm("cvt.rn.f16x2.f32 %0, %1, %2;" : "=r"(r) : "f"(hi), "f"(lo));
    return r;
}

// ---------------- angle table ----------------
__global__ void angles_kernel(const float* __restrict__ ff,
                              const float* __restrict__ fh,
                              const float* __restrict__ fw) {
    int idx = blockIdx.x * blockDim.x + threadIdx.x;
    if (idx >= L_TOK * NPAIR) return;
    int l = idx / NPAIR, j = idx % NPAIR;
    int f = l / FRAME, r = l % FRAME;
    int h = r / 30, w = r % 30;
    float a;
    if (j < 22)      a = ff[f * 22 + j];
    else if (j < 43) a = fh[h * 21 + (j - 22)];
    else             a = fw[w * 21 + (j - 43)];
    g_cos[idx] = cosf(a);
    g_sin[idx] = sinf(a);
}

// ---------------- split fp32 -> fp16 hi/lo ----------------
__global__ __launch_bounds__(256) void split_kernel(const float* __restrict__ x,
                                                    __half* __restrict__ hi,
                                                    __half* __restrict__ lo, int n) {
    int i = blockIdx.x * blockDim.x + threadIdx.x;
    if (i * 4 >= n) return;
    float4 v = *(const float4*)&x[i * 4];
    __half h0 = __float2half(v.x), h1 = __float2half(v.y);
    __half h2 = __float2half(v.z), h3 = __float2half(v.w);
    __half l0 = __float2half(v.x - __half2float(h0));
    __half l1 = __float2half(v.y - __half2float(h1));
    __half l2 = __float2half(v.z - __half2float(h2));
    __half l3 = __float2half(v.w - __half2float(h3));
    __half2* ph = (__half2*)&hi[i * 4];
    __half2* pl = (__half2*)&lo[i * 4];
    ph[0] = {h0, h1}; ph[1] = {h2, h3};
    pl[0] = {l0, l1}; pl[1] = {l2, l3};
}

// ------- fused transpose of 4 weights [K,N] -> [N,K], single fp16 -------
__global__ __launch_bounds__(256) void transpose_half4_kernel(
    const float* __restrict__ W0, const float* __restrict__ W1,
    const float* __restrict__ W2, const float* __restrict__ W3,
    __half* __restrict__ ThBase) {
    __shared__ float t[32][33];
    int z = blockIdx.z;
    const float* W = (z == 0) ? W0 : (z == 1) ? W1 : (z == 2) ? W2 : W3;
    __half* Th = ThBase + (size_t)z * DIM * DIM;
    int tx = threadIdx.x, ty = threadIdx.y;  // 32 x 8
    int x0 = blockIdx.x * 32, y0 = blockIdx.y * 32;
#pragma unroll
    for (int i = 0; i < 32; i += 8)
        t[ty + i][tx] = W[(size_t)(y0 + ty + i) * DIM + x0 + tx];
    __syncthreads();
#pragma unroll
    for (int i = 0; i < 32; i += 8)
        Th[(size_t)(x0 + ty + i) * DIM + y0 + tx] = __float2half(t[tx][ty + i]);
}

// ---------------- HMMA fp16 2-term GEMM: BK=128, 256t, 2-stage ----------------
// C = A @ W + bias ; A = Ah+Al fp16 [M,K], B = W^T fp16 single [N,K].
// Tiles: 128 rows x 256B = two 128B SW128 subtiles (16KB each).
#define GK       128
#define TILE_B   32768
#define BUF_B    (3 * TILE_B)     // Ah, Al, Bh
#define GSMEM    (1024 + 2 * BUF_B)

struct GemmArgs {
    const __half *wh0, *wh1, *wh2;
    const float *b0, *b1, *b2;
    float *o0, *o1;
    __half *ovh;                  // single fp16 output for z=2 (V)
};

__global__ __launch_bounds__(256, 1) void gemm_hmma(const __half* __restrict__ Ah,
                                                    const __half* __restrict__ Al,
                                                    GemmArgs ga) {
    extern __shared__ char dsm[];
    uint32_t raw = smem_u32(dsm);
    uint32_t sbase = (raw + 1023u) & ~1023u;

    int tid = threadIdx.x;
    int wid = tid >> 5, lane = tid & 31;
    int m0 = blockIdx.y * 128;
    int n0 = blockIdx.x * 128;

    const __half* Bh;
    const float* bias;
    float* Cf;
    if (blockIdx.z == 0)      { Bh = ga.wh0; bias = ga.b0; Cf = ga.o0; }
    else if (blockIdx.z == 1) { Bh = ga.wh1; bias = ga.b1; Cf = ga.o1; }
    else                      { Bh = ga.wh2; bias = ga.b2; Cf = nullptr; }

    const __half* srcs[3] = {Ah, Al, Bh};
    const int rbase[3] = {m0, m0, n0};

    // chunk c: 128 K-cols; tile layout = two 128B subtiles per row
    auto load_chunk = [&](int c, int buf) {
        uint32_t dst0 = sbase + (uint32_t)buf * BUF_B;
#pragma unroll
        for (int it = 0; it < 24; it++) {
            int idx = it * 256 + tid;
            int tile = idx >> 11;
            int rem = idx & 2047;
            int r = rem >> 4, g = rem & 15;
            const __half* src = srcs[tile] + (size_t)(rbase[tile] + r) * DIM + c * GK + g * 8;
            uint32_t off = (uint32_t)((g >> 3) * 16384) + SWZ128((uint32_t)(r * 128 + (g & 7) * 16));
            CP_ASYNC16(dst0 + (uint32_t)tile * TILE_B + off, src);
        }
    };

    float Creg[2][8][4];
#pragma unroll
    for (int mt = 0; mt < 2; mt++)
#pragma unroll
        for (int nf = 0; nf < 8; nf++)
#pragma unroll
            for (int j = 0; j < 4; j++) Creg[mt][nf][j] = 0.f;

    int m_base = (wid & 3) * 32;
    int n_base = (wid >> 2) * 64;
    int a_r = m_base + (lane & 7) + ((lane >> 3) & 1) * 8;
    int a_g = (lane >> 4);          // 0..1 (within 2-granule k-slice)
    int b_r = n_base + ((lane >> 4) & 1) * 8 + (lane & 7);
    int b_g = (lane >> 3) & 1;

    const int NCH = DIM / GK;  // 12
    load_chunk(0, 0); CP_COMMIT();
    load_chunk(1, 1); CP_COMMIT();

    for (int c = 0; c < NCH; c++) {
        if (c == NCH - 1) CP_WAIT0(); else CP_WAIT1();
        __syncthreads();

        int buf = c & 1;
        uint32_t sb = sbase + (uint32_t)buf * BUF_B;
        uint32_t sAh = sb, sAl = sb + TILE_B, sBh = sb + 2 * TILE_B;

#pragma unroll
        for (int ks = 0; ks < 8; ks++) {
            uint32_t ah[2][4], al[2][4], bh[16];
#pragma unroll
            for (int mt = 0; mt < 2; mt++) {
                uint32_t off = (uint32_t)((ks >> 2) * 16384) +
                    SWZ128((uint32_t)((a_r + mt * 16) * 128 + (((ks & 3) * 2 + a_g) * 16)));
                ldsm4(ah[mt], sAh + off);
                ldsm4(al[mt], sAl + off);
            }
#pragma unroll
            for (int nf2 = 0; nf2 < 4; nf2++) {
                uint32_t off = (uint32_t)((ks >> 2) * 16384) +
                    SWZ128((uint32_t)((b_r + nf2 * 16) * 128 + (((ks & 3) * 2 + b_g) * 16)));
                ldsm4(&bh[nf2 * 4], sBh + off);
            }
#pragma unroll
            for (int nf = 0; nf < 8; nf++)
#pragma unroll
                for (int mt = 0; mt < 2; mt++)
                    mma16816(Creg[mt][nf], ah[mt], &bh[nf * 2]);
#pragma unroll
            for (int nf = 0; nf < 8; nf++)
#pragma unroll
                for (int mt = 0; mt < 2; mt++)
                    mma16816(Creg[mt][nf], al[mt], &bh[nf * 2]);
        }
        __syncthreads();
        if (c + 2 < NCH) { load_chunk(c + 2, buf); CP_COMMIT(); }
    }

#pragma unroll
    for (int mt = 0; mt < 2; mt++) {
#pragma unroll
        for (int nf = 0; nf < 8; nf++) {
            int r0 = m0 + m_base + mt * 16 + (lane >> 2);
            int col = n0 + n_base + nf * 8 + (lane & 3) * 2;
            float2 bv = *(const float2*)&bias[col];
            float* cc = Creg[mt][nf];
            float c00 = cc[0] + bv.x, c01 = cc[1] + bv.y;
            float c10 = cc[2] + bv.x, c11 = cc[3] + bv.y;
            if (Cf == nullptr) {
                *(uint32_t*)&ga.ovh[(size_t)r0 * DIM + col] = pack_f16(c00, c01);
                *(uint32_t*)&ga.ovh[(size_t)(r0 + 8) * DIM + col] = pack_f16(c10, c11);
            } else {
                *(float2*)&Cf[(size_t)r0 * DIM + col] = {c00, c01};
                *(float2*)&Cf[(size_t)(r0 + 8) * DIM + col] = {c10, c11};
            }
        }
    }
}

// ---------------- fused RMSNorm + RoPE: q -> fp16 hi/lo, k -> fp16 single ---
__global__ __launch_bounds__(256) void rmsnorm_rope_split2(
    const float* __restrict__ xq, const float* __restrict__ xk,
    const float* __restrict__ gqv, const float* __restrict__ gkv,
    __half* __restrict__ qh, __half* __restrict__ ql,
    __half* __restrict__ kh) {
    int row = blockIdx.x;
    int which = blockIdx.y;
    const float* xp = (which ? xk : xq) + (size_t)row * DIM;
    const float* g = which ? gkv : gqv;
    float outscale = which ? 1.0f : 0.08838834764831845f;
    int tid = threadIdx.x;

    float ss = 0.f;
    for (int i = tid; i < DIM; i += 256) {
        float v = xp[i];
        ss += v * v;
    }
    __shared__ float red[8];
#pragma unroll
    for (int m = 16; m; m >>= 1) ss += __shfl_xor_sync(0xffffffffu, ss, m);
    if ((tid & 31) == 0) red[tid >> 5] = ss;
    __syncthreads();
    if (tid < 8) {
        float v = red[tid];
#pragma unroll
        for (int m = 4; m; m >>= 1) v += __shfl_xor_sync(0xffu, v, m);
        if (tid == 0) red[0] = rsqrtf(v * (1.0f / DIM) + 1e-6f);
    }
    __syncthreads();
    float scale = red[0];

    for (int p = tid; p < NH * NPAIR; p += 256) {
        int head = p >> 6, j = p & 63;
        int i0 = head * HD + 2 * j;
        float2 v = *(const float2*)&xp[i0];
        float2 gv = *(const float2*)&g[i0];
        float xr = v.x * scale * gv.x;
        float xi = v.y * scale * gv.y;
        float c = g_cos[row * NPAIR + j];
        float s = g_sin[row * NPAIR + j];
        float yr = (xr * c - xi * s) * outscale;
        float yi = (xr * s + xi * c) * outscale;
        if (which == 0) {
            __half hr = __float2half(yr);
            __half hi2 = __float2half(yi);
            __half lr = __float2half(yr - __half2float(hr));
            __half li = __float2half(yi - __half2float(hi2));
            *(__half2*)&qh[(size_t)row * DIM + i0] = {hr, hi2};
            *(__half2*)&ql[(size_t)row * DIM + i0] = {lr, li};
        } else {
            *(__half2*)&kh[(size_t)row * DIM + i0] = {__float2half(yr), __float2half(yi)};
        }
    }
}

// ---------------- persistent fp16 flash attention (delayed PV) --------------
#define ATT_Q    0
#define ATT_K    65536
#define ATT_V    98304
#define ATT_WS   147456
#define ATT_SMEM (147456 + 32)

__global__ __launch_bounds__(256, 1) void attention_hmma(
    const __half* __restrict__ Qh, const __half* __restrict__ Ql,
    const __half* __restrict__ Kh, const __half* __restrict__ Vh,
    __half* __restrict__ Oh, __half* __restrict__ Ol) {
    extern __shared__ char dsm[];
    uint32_t sbase = smem_u32(dsm);
    int* wslot = (int*)(dsm + ATT_WS);

    int tid = threadIdx.x, wid = tid >> 5, lane = tid & 31;

    int a_r = wid * 16 + (lane & 7) + ((lane >> 3) & 1) * 8;
    int a_half = lane >> 4;
    int b_r = ((lane >> 4) & 1) * 8 + (lane & 7);
    int b_half = (lane >> 3) & 1;
    int v_r = (lane & 15);
    int vg = (lane >> 4);

    for (;;) {
        if (tid == 0) wslot[0] = atomicAdd(&g_work, 1);
        __syncthreads();
        int item = wslot[0];
        if (item >= N_ITEM) return;
        int qb = N_QB - 1 - item / NH;
        int h = item % NH;
        int q0 = qb * 128;

        {
            const __half* gq[2] = {Qh, Ql};
#pragma unroll
            for (int op = 0; op < 2; op++) {
                const __half* src = gq[op] + (size_t)q0 * DIM + h * HD;
                uint32_t dst = sbase + ATT_Q + (uint32_t)op * 32768;
#pragma unroll
                for (int it = 0; it < 8; it++) {
                    int idx = it * 256 + tid;
                    int r = idx >> 4, gg = idx & 15;
                    uint32_t off = (uint32_t)((gg >> 3) * 16384) + SWZ128((uint32_t)(r * 128 + (gg & 7) * 16));
                    CP_ASYNC16(dst + off, src + (size_t)r * DIM + gg * 8);
                }
            }
            CP_COMMIT();
        }

        auto load_kv = [&](int t) {
            int k0 = t * 64;
            uint32_t kdst = sbase + ATT_K + (uint32_t)(t & 1) * 16384;
            uint32_t vdst = sbase + ATT_V + (uint32_t)(t % 3) * 16384;
            const __half* ksrc = Kh + (size_t)k0 * DIM + h * HD;
            const __half* vsrc = Vh + (size_t)k0 * DIM + h * HD;
#pragma unroll
            for (int it = 0; it < 4; it++) {
                int idx = it * 256 + tid;
                int r = idx >> 4, gg = idx & 15;
                uint32_t off = (uint32_t)((gg >> 3) * 8192) + SWZ128((uint32_t)(r * 128 + (gg & 7) * 16));
                CP_ASYNC16(kdst + off, ksrc + (size_t)r * DIM + gg * 8);
                CP_ASYNC16(vdst + off, vsrc + (size_t)r * DIM + gg * 8);
            }
        };

        float O[16][4];
#pragma unroll
        for (int i = 0; i < 16; i++)
#pragma unroll
            for (int j = 0; j < 4; j++) O[i][j] = 0.f;
        float m0 = -1e30f, m1 = -1e30f, l0 = 0.f, l1 = 0.f;
        uint32_t PhP[4][4], PlP[4][4];

        int r0g = q0 + wid * 16 + (lane >> 2);
        int fr0 = r0g / FRAME, fr1 = (r0g + 8) / FRAME;
        int blkmin_f = q0 / FRAME;
        int fqmax = (q0 + 127) / FRAME;
        int ntile = ((fqmax + 1) * FRAME + 63) >> 6;

        load_kv(0); CP_COMMIT();
        load_kv(1); CP_COMMIT();

        for (int t = 0; t < ntile; t++) {
            if (t == ntile - 1) CP_WAIT0(); else CP_WAIT1();
            __syncthreads();

            int k0 = t * 64;
            uint32_t bKh = sbase + ATT_K + (uint32_t)(t & 1) * 16384;

            float S[8][4];
#pragma unroll
            for (int i = 0; i < 8; i++)
#pragma unroll
                for (int j = 0; j < 4; j++) S[i][j] = 0.f;

#pragma unroll
            for (int ks = 0; ks < 8; ks++) {
                uint32_t qa[4], ql4[4], kh4[16];
                uint32_t gq16 = (uint32_t)(((ks & 3) * 2 + a_half) * 16);
                uint32_t aoff = (uint32_t)((ks >> 2) * 16384) + SWZ128((uint32_t)(a_r * 128) + gq16);
                ldsm4(qa, sbase + ATT_Q + aoff);
                ldsm4(ql4, sbase + ATT_Q + 32768 + aoff);
                uint32_t gk16 = (uint32_t)(((ks & 3) * 2 + b_half) * 16);
#pragma unroll
                for (int nb = 0; nb < 4; nb++) {
                    uint32_t boff = (uint32_t)((ks >> 2) * 8192) +
                                    SWZ128((uint32_t)((nb * 16 + b_r) * 128) + gk16);
                    ldsm4(&kh4[nb * 4], bKh + boff);
                }
#pragma unroll
                for (int nf = 0; nf < 8; nf++) mma16816(S[nf], qa, &kh4[nf * 2]);
#pragma unroll
                for (int nf = 0; nf < 8; nf++) mma16816(S[nf], ql4, &kh4[nf * 2]);
            }

            if (t > 0) {
                uint32_t bVh = sbase + ATT_V + (uint32_t)((t - 1) % 3) * 16384;
#pragma unroll
                for (int j = 0; j < 4; j++) {
#pragma unroll
                    for (int dp = 0; dp < 4; dp++) {
                        int db0 = 2 * dp, db1 = 2 * dp + 1;
                        uint32_t row = (uint32_t)((j * 16 + v_r) * 128);
                        uint32_t voff0 = (uint32_t)((db0 >> 2) * 8192) +
                                         SWZ128(row + (uint32_t)(((db0 & 3) * 2 + vg) * 16));
                        uint32_t voff1 = (uint32_t)((db1 >> 2) * 8192) +
                                         SWZ128(row + (uint32_t)(((db1 & 3) * 2 + vg) * 16));
                        uint32_t vh_a[4], vh_b[4];
                        ldsm4t(vh_a, bVh + voff0);
                        ldsm4t(vh_b, bVh + voff1);
                        float* o0 = O[4 * dp + 0];
                        float* o1 = O[4 * dp + 1];
                        float* o2 = O[4 * dp + 2];
                        float* o3 = O[4 * dp + 3];
                        mma16816(o0, PhP[j], &vh_a[0]);
                        mma16816(o1, PhP[j], &vh_a[2]);
                        mma16816(o2, PhP[j], &vh_b[0]);
                        mma16816(o3, PhP[j], &vh_b[2]);
                        mma16816(o0, PlP[j], &vh_a[0]);
                        mma16816(o1, PlP[j], &vh_a[2]);
                        mma16816(o2, PlP[j], &vh_b[0]);
                        mma16816(o3, PlP[j], &vh_b[2]);
                    }
                }
            }

            if ((k0 + 63) / FRAME > blkmin_f) {
#pragma unroll
                for (int nf = 0; nf < 8; nf++) {
                    int c = k0 + nf * 8 + 2 * (lane & 3);
                    int cf0 = c / FRAME, cf1 = (c + 1) / FRAME;
                    if (cf0 > fr0) S[nf][0] = -1e30f;
                    if (cf1 > fr0) S[nf][1] = -1e30f;
                    if (cf0 > fr1) S[nf][2] = -1e30f;
                    if (cf1 > fr1) S[nf][3] = -1e30f;
                }
            }

            float mx0 = -1e30f, mx1 = -1e30f;
#pragma unroll
            for (int nf = 0; nf < 8; nf++) {
                mx0 = fmaxf(mx0, fmaxf(S[nf][0], S[nf][1]));
                mx1 = fmaxf(mx1, fmaxf(S[nf][2], S[nf][3]));
            }
            mx0 = fmaxf(mx0, __shfl_xor_sync(0xffffffffu, mx0, 1));
            mx0 = fmaxf(mx0, __shfl_xor_sync(0xffffffffu, mx0, 2));
            mx1 = fmaxf(mx1, __shfl_xor_sync(0xffffffffu, mx1, 1));
            mx1 = fmaxf(mx1, __shfl_xor_sync(0xffffffffu, mx1, 2));
            float mn0 = fmaxf(m0, mx0), mn1 = fmaxf(m1, mx1);
            float al0 = __expf(m0 - mn0), al1 = __expf(m1 - mn1);
            m0 = mn0; m1 = mn1;
#pragma unroll
            for (int i = 0; i < 16; i++) {
                O[i][0] *= al0; O[i][1] *= al0;
                O[i][2] *= al1; O[i][3] *= al1;
            }

            float ps0 = 0.f, ps1 = 0.f;
#pragma unroll
            for (int j = 0; j < 4; j++) {
                float p00 = __expf(S[2 * j][0] - mn0);
                float p01 = __expf(S[2 * j][1] - mn0);
                float p02 = __expf(S[2 * j][2] - mn1);
                float p03 = __expf(S[2 * j][3] - mn1);
                float p10 = __expf(S[2 * j + 1][0] - mn0);
                float p11 = __expf(S[2 * j + 1][1] - mn0);
                float p12 = __expf(S[2 * j + 1][2] - mn1);
                float p13 = __expf(S[2 * j + 1][3] - mn1);
                ps0 += (p00 + p01) + (p10 + p11);
                ps1 += (p02 + p03) + (p12 + p13);
                PhP[j][0] = pack_f16(p00, p01);
                PhP[j][1] = pack_f16(p02, p03);
                PhP[j][2] = pack_f16(p10, p11);
                PhP[j][3] = pack_f16(p12, p13);
                __half2 h0 = *(__half2*)&PhP[j][0];
                __half2 h1 = *(__half2*)&PhP[j][1];
                __half2 h2 = *(__half2*)&PhP[j][2];
                __half2 h3 = *(__half2*)&PhP[j][3];
                PlP[j][0] = pack_f16(p00 - __half2float(h0.x), p01 - __half2float(h0.y));
                PlP[j][1] = pack_f16(p02 - __half2float(h1.x), p03 - __half2float(h1.y));
                PlP[j][2] = pack_f16(p10 - __half2float(h2.x), p11 - __half2float(h2.y));
                PlP[j][3] = pack_f16(p12 - __half2float(h3.x), p13 - __half2float(h3.y));
            }
            ps0 += __shfl_xor_sync(0xffffffffu, ps0, 1);
            ps0 += __shfl_xor_sync(0xffffffffu, ps0, 2);
            ps1 += __shfl_xor_sync(0xffffffffu, ps1, 1);
            ps1 += __shfl_xor_sync(0xffffffffu, ps1, 2);
            l0 = l0 * al0 + ps0;
            l1 = l1 * al1 + ps1;

            __syncthreads();
            if (t + 2 < ntile) { load_kv(t + 2); CP_COMMIT(); }
        }

        {
            uint32_t bVh = sbase + ATT_V + (uint32_t)((ntile - 1) % 3) * 16384;
#pragma unroll
            for (int j = 0; j < 4; j++) {
#pragma unroll
                for (int dp = 0; dp < 4; dp++) {
                    int db0 = 2 * dp, db1 = 2 * dp + 1;
                    uint32_t row = (uint32_t)((j * 16 + v_r) * 128);
                    uint32_t voff0 = (uint32_t)((db0 >> 2) * 8192) +
                                     SWZ128(row + (uint32_t)(((db0 & 3) * 2 + vg) * 16));
                    uint32_t voff1 = (uint32_t)((db1 >> 2) * 8192) +
                                     SWZ128(row + (uint32_t)(((db1 & 3) * 2 + vg) * 16));
                    uint32_t vh_a[4], vh_b[4];
                    ldsm4t(vh_a, bVh + voff0);
                    ldsm4t(vh_b, bVh + voff1);
                    float* o0 = O[4 * dp + 0];
                    float* o1 = O[4 * dp + 1];
                    float* o2 = O[4 * dp + 2];
                    float* o3 = O[4 * dp + 3];
                    mma16816(o0, PhP[j], &vh_a[0]);
                    mma16816(o1, PhP[j], &vh_a[2]);
                    mma16816(o2, PhP[j], &vh_b[0]);
                    mma16816(o3, PhP[j], &vh_b[2]);
                    mma16816(o0, PlP[j], &vh_a[0]);
                    mma16816(o1, PlP[j], &vh_a[2]);
                    mma16816(o2, PlP[j], &vh_b[0]);
                    mma16816(o3, PlP[j], &vh_b[2]);
                }
            }
        }

        float inv0 = 1.0f / l0, inv1 = 1.0f / l1;
        int row0 = q0 + wid * 16 + (lane >> 2);
#pragma unroll
        for (int nf = 0; nf < 16; nf++) {
            int col = h * HD + nf * 8 + 2 * (lane & 3);
            float o00 = O[nf][0] * inv0, o01 = O[nf][1] * inv0;
            float o10 = O[nf][2] * inv1, o11 = O[nf][3] * inv1;
            uint32_t h0 = pack_f16(o00, o01);
            uint32_t h1 = pack_f16(o10, o11);
            __half2 hh0 = *(__half2*)&h0;
            __half2 hh1 = *(__half2*)&h1;
            uint32_t lo0 = pack_f16(o00 - __half2float(hh0.x), o01 - __half2float(hh0.y));
            uint32_t lo1 = pack_f16(o10 - __half2float(hh1.x), o11 - __half2float(hh1.y));
            *(uint32_t*)&Oh[(size_t)row0 * DIM + col] = h0;
            *(uint32_t*)&Ol[(size_t)row0 * DIM + col] = lo0;
            *(uint32_t*)&Oh[(size_t)(row0 + 8) * DIM + col] = h1;
            *(uint32_t*)&Ol[(size_t)(row0 + 8) * DIM + col] = lo1;
        }
    }
}

// ---------------- launch ----------------
extern "C" void kernel_launch(void* const* d_in, const int* in_sizes, int n_in,
                              void* d_out, int out_size) {
    const float* x  = (const float*)d_in[0];
    const float* Wq = (const float*)d_in[1];
    const float* bq = (const float*)d_in[2];
    const float* Wk = (const float*)d_in[3];
    const float* bk = (const float*)d_in[4];
    const float* Wv = (const float*)d_in[5];
    const float* bv = (const float*)d_in[6];
    const float* Wo = (const float*)d_in[7];
    const float* bo = (const float*)d_in[8];
    const float* gq = (const float*)d_in[9];
    const float* gk = (const float*)d_in[10];
    const float* ff = (const float*)d_in[11];
    const float* fh = (const float*)d_in[12];
    const float* fw = (const float*)d_in[13];
    float* out = (float*)d_out;

    float *qp, *kp;
    __half *ah, *al, *qh, *ql, *kh, *vh, *whb;
    int* workp;
    cudaGetSymbolAddress((void**)&qp, g_q);
    cudaGetSymbolAddress((void**)&kp, g_k);
    cudaGetSymbolAddress((void**)&ah, g_ah);
    cudaGetSymbolAddress((void**)&al, g_al);
    cudaGetSymbolAddress((void**)&whb, g_wh);
    cudaGetSymbolAddress((void**)&qh, g_qh);
    cudaGetSymbolAddress((void**)&ql, g_ql);
    cudaGetSymbolAddress((void**)&kh, g_kh);
    cudaGetSymbolAddress((void**)&vh, g_vh);
    cudaGetSymbolAddress((void**)&workp, g_work);

    cudaFuncSetAttribute(gemm_hmma,
                         cudaFuncAttributeMaxDynamicSharedMemorySize, GSMEM);
    cudaFuncSetAttribute(attention_hmma,
                         cudaFuncAttributeMaxDynamicSharedMemorySize, ATT_SMEM);

    cudaMemsetAsync(workp, 0, sizeof(int));

    angles_kernel<<<(L_TOK * NPAIR + 255) / 256, 256>>>(ff, fh, fw);

    const int NELT = L_TOK * DIM;
    split_kernel<<<(NELT / 4 + 255) / 256, 256>>>(x, ah, al, NELT);

    transpose_half4_kernel<<<dim3(DIM / 32, DIM / 32, 4), dim3(32, 8)>>>(
        Wq, Wk, Wv, Wo, whb);

    const size_t WSZ = (size_t)DIM * DIM;
    GemmArgs ga;
    ga.wh0 = whb;           ga.b0 = bq; ga.o0 = qp;
    ga.wh1 = whb + WSZ;     ga.b1 = bk; ga.o1 = kp;
    ga.wh2 = whb + 2 * WSZ; ga.b2 = bv;
    ga.ovh = vh;
    gemm_hmma<<<dim3(DIM / 128, L_TOK / 128, 3), 256, GSMEM>>>(ah, al, ga);

    rmsnorm_rope_split2<<<dim3(L_TOK, 2), 256>>>(qp, kp, gq, gk, qh, ql, kh);

    attention_hmma<<<148, 256, ATT_SMEM>>>(qh, ql, kh, vh, ah, al);

    GemmArgs go;
    go.wh0 = whb + 3 * WSZ; go.b0 = bo; go.o0 = out;
    go.wh1 = go.wh0; go.b1 = bo; go.o1 = out;
    go.wh2 = go.wh0; go.b2 = bo;
    go.ovh = vh;
    gemm_hmma<<<dim3(DIM / 128, L_TOK / 128, 1), 256, GSMEM>>>(ah, al, go);
}